// round 7
// baseline (speedup 1.0000x reference)
#include <cuda_runtime.h>
#include <cuda_fp16.h>
#include <math.h>
#include <stdint.h>

#define BB   2
#define SS   2048
#define DD   2048
#define HH   16
#define HD   128
#define FF   8192
#define MM   (BB*SS)          // 4096
#define QKVW (3*DD)           // 6144

// ---------------- fp32 scratch ----------------
__device__ float g_qkv[MM*QKVW];
__device__ float g_a1 [MM*FF];

// ---------------- fp16 packed scratch ----------------------------------------
// A-operand (activations): [rows/128][K/64][2(hi,lo)][128][64], SW128 swizzled
__device__ __half g_xn2 [(size_t)MM*2*DD];
__device__ __half g_att2[(size_t)MM*2*DD];
__device__ __half g_h2  [(size_t)MM*2*DD];
__device__ __half g_gg2 [(size_t)MM*2*FF];
// B-operand (weights): [rows/128][K/64][128][64] hi-only, SW128 swizzled
__device__ __half g_wqkv2[(size_t)QKVW*DD];
__device__ __half g_wout2[(size_t)DD*DD];
__device__ __half g_w12 [(size_t)FF*DD];
__device__ __half g_w32 [(size_t)FF*DD];
__device__ __half g_w22 [(size_t)DD*FF];

// ---------------- PTX helpers -------------------------------------------------
__device__ __forceinline__ uint32_t smem_u32(const void* p) {
    uint32_t a;
    asm("{ .reg .u64 t; cvta.to.shared.u64 t, %1; cvt.u32.u64 %0, t; }" : "=r"(a) : "l"(p));
    return a;
}
__device__ __forceinline__ uint32_t elect_one() {
    uint32_t p;
    asm volatile("{ .reg .pred p; elect.sync _|p, 0xFFFFFFFF; selp.b32 %0,1,0,p; }" : "=r"(p));
    return p;
}
__device__ __forceinline__ float to_tf32(float x) {
    uint32_t t;
    asm("cvt.rna.tf32.f32 %0, %1;" : "=r"(t) : "f"(x));
    return __uint_as_float(t);
}
#define MBAR_INIT(a, c) \
    asm volatile("mbarrier.init.shared.b64 [%0], %1;" :: "r"(a), "r"(c) : "memory")
#define MBAR_EXPECT(a, b) \
    asm volatile("mbarrier.arrive.expect_tx.shared.b64 _, [%0], %1;" :: "r"(a), "r"(b) : "memory")
#define MBAR_ARRIVE(a) \
    asm volatile("mbarrier.arrive.shared.b64 _, [%0];" :: "r"(a) : "memory")
#define MBAR_WAIT(a, ph) do { uint32_t _m=(a), _p=(ph), _d;                                   \
    asm volatile("{ .reg .pred p; mbarrier.try_wait.parity.acquire.cta.shared::cta.b64 p, [%1], %2; selp.b32 %0,1,0,p; }" \
                 : "=r"(_d) : "r"(_m), "r"(_p) : "memory");                                   \
    if (!_d) {                                                                                \
      asm volatile("{ .reg .pred P1; WL%=: mbarrier.try_wait.parity.acquire.cta.shared::cta.b64 P1, [%0], %1, 0x989680; @P1 bra.uni WD%=; bra.uni WL%=; WD%=: }" \
                   :: "r"(_m), "r"(_p) : "memory"); } } while(0)
#define BULK_G2S(d, s, n, m) \
    asm volatile("cp.async.bulk.shared::cta.global.mbarrier::complete_tx::bytes [%0], [%1], %2, [%3];" \
                 :: "r"(d), "l"(s), "r"(n), "r"(m) : "memory")
#define LDSM_X4(r0, r1, r2, r3, a) \
    asm volatile("ldmatrix.sync.aligned.m8n8.x4.shared.b16 {%0,%1,%2,%3}, [%4];" \
                 : "=r"(r0), "=r"(r1), "=r"(r2), "=r"(r3) : "r"(a))
#define MMA16816H(d, av, bv) \
    asm volatile("mma.sync.aligned.m16n8k16.row.col.f32.f16.f16.f32 " \
                 "{%0,%1,%2,%3}, {%4,%5,%6,%7}, {%8,%9}, {%0,%1,%2,%3};" \
                 : "+f"((d)[0]), "+f"((d)[1]), "+f"((d)[2]), "+f"((d)[3]) \
                 : "r"((av)[0]), "r"((av)[1]), "r"((av)[2]), "r"((av)[3]), \
                   "r"((bv)[0]), "r"((bv)[1]))
#define MMA1688TF(d, a0, a1, a2, a3, b0, b1) \
    asm volatile("mma.sync.aligned.m16n8k8.row.col.f32.tf32.tf32.f32 " \
                 "{%0,%1,%2,%3}, {%4,%5,%6,%7}, {%8,%9}, {%0,%1,%2,%3};" \
                 : "+f"((d)[0]), "+f"((d)[1]), "+f"((d)[2]), "+f"((d)[3]) \
                 : "r"(a0), "r"(a1), "r"(a2), "r"(a3), "r"(b0), "r"(b1))

// ---------------- fp16 split/pack helpers -------------------------------------
__device__ __forceinline__ void split_pair(float v0, float v1, uint32_t& hi, uint32_t& lo) {
    __half h0 = __float2half_rn(v0), h1 = __float2half_rn(v1);
    __half l0 = __float2half_rn(v0 - __half2float(h0));
    __half l1 = __float2half_rn(v1 - __half2float(h1));
    hi = (uint32_t)__half_as_ushort(h0) | ((uint32_t)__half_as_ushort(h1) << 16);
    lo = (uint32_t)__half_as_ushort(l0) | ((uint32_t)__half_as_ushort(l1) << 16);
}
// packed A store, 2 consecutive cols (n even)
__device__ __forceinline__ void pack2A(char* base, int ktK, int m, int n, float v0, float v1) {
    const int mt = m >> 7, mr = m & 127;
    const int kt = n >> 6, c = n & 63;
    const size_t tb = ((size_t)mt * ktK + kt) * 32768;
    uint32_t off = (uint32_t)(mr * 128 + c * 2);
    off ^= (off >> 3) & 0x70;
    uint32_t hi, lo;
    split_pair(v0, v1, hi, lo);
    *(uint32_t*)(base + tb + off)         = hi;
    *(uint32_t*)(base + tb + 16384 + off) = lo;
}
// packed A store, 4 consecutive cols (n % 4 == 0)
__device__ __forceinline__ void pack4A(char* base, int ktK, int m, int n, float4 v) {
    const int mt = m >> 7, mr = m & 127;
    const int kt = n >> 6, c = n & 63;
    const size_t tb = ((size_t)mt * ktK + kt) * 32768;
    uint32_t off = (uint32_t)(mr * 128 + c * 2);
    off ^= (off >> 3) & 0x70;
    uint32_t h0, l0, h1, l1;
    split_pair(v.x, v.y, h0, l0);
    split_pair(v.z, v.w, h1, l1);
    *(uint2*)(base + tb + off)         = make_uint2(h0, h1);
    *(uint2*)(base + tb + 16384 + off) = make_uint2(l0, l1);
}

// ---------------- RMSNorm -> packed fp16 split --------------------------------
__global__ __launch_bounds__(256) void rmsnorm_pack(
    const float* __restrict__ x, const float* __restrict__ w, __half* __restrict__ dst)
{
    const int row = blockIdx.x;
    const float4* xr = (const float4*)(x + (size_t)row * DD);
    float4 a = xr[threadIdx.x];
    float4 b = xr[threadIdx.x + 256];
    float ss = a.x*a.x + a.y*a.y + a.z*a.z + a.w*a.w
             + b.x*b.x + b.y*b.y + b.z*b.z + b.w*b.w;
    #pragma unroll
    for (int o = 16; o; o >>= 1) ss += __shfl_xor_sync(0xffffffffu, ss, o);
    __shared__ float sred[8];
    if ((threadIdx.x & 31) == 0) sred[threadIdx.x >> 5] = ss;
    __syncthreads();
    float tot = sred[0]+sred[1]+sred[2]+sred[3]+sred[4]+sred[5]+sred[6]+sred[7];
    float sc = rsqrtf(tot * (1.0f / DD) + 1e-5f);

    const float4* wr = (const float4*)w;
    #pragma unroll
    for (int g = 0; g < 2; g++) {
        const int gi = threadIdx.x + g*256;
        float4 v = (g == 0) ? a : b;
        float4 wv = wr[gi];
        v.x *= sc * wv.x; v.y *= sc * wv.y; v.z *= sc * wv.z; v.w *= sc * wv.w;
        pack4A((char*)dst, DD/64, row, gi*4, v);
    }
}

// ---------------- weight fp32 -> fp16 hi-only tile-packed ---------------------
__global__ __launch_bounds__(256) void convW(
    const float* __restrict__ src, __half* __restrict__ dst, int K, int total4)
{
    int gid = blockIdx.x * 256 + threadIdx.x;
    if (gid >= total4) return;
    const int kq = K >> 2;
    const int m  = gid / kq;
    const int k  = (gid - m * kq) << 2;

    float4 v = *(const float4*)(src + (size_t)m * K + k);
    __half h0 = __float2half_rn(v.x), h1 = __float2half_rn(v.y);
    __half h2 = __float2half_rn(v.z), h3 = __float2half_rn(v.w);
    uint2 hp = make_uint2((uint32_t)__half_as_ushort(h0) | ((uint32_t)__half_as_ushort(h1) << 16),
                          (uint32_t)__half_as_ushort(h2) | ((uint32_t)__half_as_ushort(h3) << 16));

    const int ktK = K >> 6;
    const int mt = m >> 7, mr = m & 127;
    const int kt = k >> 6, c = k & 63;
    size_t base = ((size_t)mt * ktK + kt) * 16384;
    uint32_t off = (uint32_t)(mr * 128 + c * 2);
    off ^= (off >> 3) & 0x70;
    *(uint2*)((char*)dst + base + off) = hp;
}

// ---------------- fp16 mma.sync GEMM: C = A(hi+lo)·B(hi)^T --------------------
// A packed [mt][ktK][2][128][64]; B packed [nt][ktK][128][64].
// 128x128 tile, 8 math warps + 1 producer. Stage = A(32KB) + B(16KB).
// out: P!=null -> packed fp16-split A-format (for next GEMM); else fp32 C.
// mode 0: v(+bias) ; mode 1: E + relu(v+bias) ; mode 2: E + v + bias
#define G_STG    4
#define G_TB     16384
#define G_STAGE  (3*G_TB)
#define G_SMEM   (1024 + G_STG*G_STAGE)       // 197632
#define GROUP_M  8

__global__ __launch_bounds__(288, 1) void gemm_mma(
    const __half* __restrict__ A2, const __half* __restrict__ B2,
    const float* __restrict__ bias, const float* __restrict__ E,
    float* __restrict__ C, __half* __restrict__ P,
    int N, int ktK, int mode)
{
    extern __shared__ char sm[];
    const uint32_t sb = smem_u32(sm);
    const int tid = threadIdx.x, wid = tid >> 5, lane = tid & 31;

    const uint32_t MFULL  = sb;
    const uint32_t MEMPTY = sb + 256;
    const uint32_t SPIPE  = sb + 1024;

    if (tid == 0) {
        #pragma unroll
        for (int s = 0; s < G_STG; s++) { MBAR_INIT(MFULL + s*8, 1); MBAR_INIT(MEMPTY + s*8, 8); }
    }
    __syncthreads();

    const int gridN = gridDim.x;
    const int bid   = blockIdx.y * gridN + blockIdx.x;
    const int tpg   = GROUP_M * gridN;
    const int grp   = bid / tpg, rem = bid - grp * tpg;
    const int mt    = grp * GROUP_M + (rem % GROUP_M);
    const int nt    = rem / GROUP_M;

    float d[2][8][4];
    #pragma unroll
    for (int a = 0; a < 2; a++)
        #pragma unroll
        for (int b = 0; b < 8; b++)
            #pragma unroll
            for (int c = 0; c < 4; c++) d[a][b][c] = 0.f;

    if (wid == 8) {
        if (elect_one()) {
            const char* Ag = (const char*)A2 + (size_t)mt * ktK * 2 * G_TB;
            const char* Bg = (const char*)B2 + (size_t)nt * ktK * G_TB;
            int s = 0, ph = 1;
            for (int kt = 0; kt < ktK; kt++) {
                MBAR_WAIT(MEMPTY + s*8, ph);
                MBAR_EXPECT(MFULL + s*8, G_STAGE);
                const uint32_t dst = SPIPE + s*G_STAGE;
                BULK_G2S(dst,          Ag + (size_t)kt*2*G_TB, 2*G_TB, MFULL + s*8);
                BULK_G2S(dst + 2*G_TB, Bg + (size_t)kt*G_TB,   G_TB,   MFULL + s*8);
                if (++s == G_STG) { s = 0; ph ^= 1; }
            }
        }
    } else {
        const int wm = (wid & 3) * 32;
        const int wn = (wid >> 2) * 64;
        const uint32_t rsub   = (uint32_t)(((lane >> 3) & 1) * 8 + (lane & 7));
        const uint32_t ksel   = (uint32_t)((lane >> 4) * 16);
        const uint32_t cmask  = (uint32_t)((lane & 7) << 4);
        const uint32_t aRowOff = (uint32_t)(wm + rsub) * 128;
        const uint32_t bRowOff = (uint32_t)(wn + rsub) * 128;

        int s = 0, ph = 0;
        for (int kt = 0; kt < ktK; kt++) {
            MBAR_WAIT(MFULL + s*8, ph);
            const uint32_t sa  = SPIPE + s*G_STAGE;           // A hi
            const uint32_t sal = sa + G_TB;                   // A lo
            const uint32_t sbb = sa + 2*G_TB;                 // B hi
            #pragma unroll
            for (int kk4 = 0; kk4 < 4; kk4++) {
                const uint32_t ko = (uint32_t)(kk4*32 + ksel) ^ cmask;
                uint32_t bf[8][2];
                #pragma unroll
                for (int ng = 0; ng < 4; ng++) {
                    uint32_t t0, t1, t2, t3;
                    LDSM_X4(t0, t1, t2, t3, sbb + bRowOff + ng*2048 + ko);
                    bf[2*ng][0] = t0; bf[2*ng+1][0] = t1;
                    bf[2*ng][1] = t2; bf[2*ng+1][1] = t3;
                }
                uint32_t af[2][4];
                #pragma unroll
                for (int mi = 0; mi < 2; mi++)
                    LDSM_X4(af[mi][0], af[mi][1], af[mi][2], af[mi][3],
                            sa + aRowOff + mi*2048 + ko);
                #pragma unroll
                for (int mi = 0; mi < 2; mi++)
                    #pragma unroll
                    for (int ni = 0; ni < 8; ni++)
                        MMA16816H(d[mi][ni], af[mi], bf[ni]);
                #pragma unroll
                for (int mi = 0; mi < 2; mi++)
                    LDSM_X4(af[mi][0], af[mi][1], af[mi][2], af[mi][3],
                            sal + aRowOff + mi*2048 + ko);
                #pragma unroll
                for (int mi = 0; mi < 2; mi++)
                    #pragma unroll
                    for (int ni = 0; ni < 8; ni++)
                        MMA16816H(d[mi][ni], af[mi], bf[ni]);
            }
            if (lane == 0) MBAR_ARRIVE(MEMPTY + s*8);
            if (++s == G_STG) { s = 0; ph ^= 1; }
        }
    }

    __syncthreads();

    float* st = (float*)(sm + 1024);
    if (wid < 8) {
        const int wm = (wid & 3) * 32;
        const int wn = (wid >> 2) * 64;
        const int r0 = lane >> 2;
        const int cc = (lane & 3) * 2;
        #pragma unroll
        for (int mi = 0; mi < 2; mi++)
            #pragma unroll
            for (int ni = 0; ni < 8; ni++) {
                const int r = wm + mi*16 + r0;
                const int c = wn + ni*8 + cc;
                st[r*132 + c]       = d[mi][ni][0];
                st[r*132 + c + 1]   = d[mi][ni][1];
                st[(r+8)*132 + c]   = d[mi][ni][2];
                st[(r+8)*132 + c+1] = d[mi][ni][3];
            }
    }
    __syncthreads();

    if (tid < 256) {
        const int r0 = tid >> 5;
        const int c  = (tid & 31) * 4;
        const int n  = nt*128 + c;
        float4 bv = make_float4(0.f, 0.f, 0.f, 0.f);
        if (bias) bv = *(const float4*)(bias + n);
        #pragma unroll 4
        for (int rp = 0; rp < 16; rp++) {
            const int r = rp*8 + r0;
            const size_t idx = (size_t)(mt*128 + r) * N + n;
            float4 v = *(float4*)&st[r*132 + c];
            v.x += bv.x; v.y += bv.y; v.z += bv.z; v.w += bv.w;
            if (mode == 1) {
                float4 e = *(const float4*)(E + idx);
                v.x = e.x + fmaxf(v.x, 0.f); v.y = e.y + fmaxf(v.y, 0.f);
                v.z = e.z + fmaxf(v.z, 0.f); v.w = e.w + fmaxf(v.w, 0.f);
            } else if (mode == 2) {
                float4 e = *(const float4*)(E + idx);
                v.x += e.x; v.y += e.y; v.z += e.z; v.w += e.w;
            }
            if (P) pack4A((char*)P, N >> 6, mt*128 + r, n, v);
            else   *(float4*)(C + idx) = v;
        }
    }
}

// ---------------- tf32 tensor-core causal flash attention -> packed -----------
#define AT_SMEMF (3*64*132 + 64*68 + 128)
__global__ __launch_bounds__(256) void attn_tc(
    const float* __restrict__ qkv, __half* __restrict__ outP)
{
    extern __shared__ float s[];
    float* Qs = s;
    float* Ks = Qs + 64*132;
    float* Vs = Ks + 64*132;
    float* Sb = Vs + 64*132;
    float* Cr = Sb + 64*68;
    float* Ll = Cr + 64;

    const int tid = threadIdx.x, wid = tid >> 5, lane = tid & 31;
    const int qt = blockIdx.x, hh = blockIdx.y, bb = blockIdx.z;
    const int q0 = qt * 64;

    #pragma unroll
    for (int i = 0; i < 8; i++) {
        int id = i*256 + tid;
        int rr = id >> 5, c4 = (id & 31) * 4;
        float4 v = *(const float4*)(qkv + (size_t)(bb*SS + q0 + rr) * QKVW + hh*HD + c4);
        Qs[rr*132 + c4 + 0] = to_tf32(v.x * 0.08838834764831845f);
        Qs[rr*132 + c4 + 1] = to_tf32(v.y * 0.08838834764831845f);
        Qs[rr*132 + c4 + 2] = to_tf32(v.z * 0.08838834764831845f);
        Qs[rr*132 + c4 + 3] = to_tf32(v.w * 0.08838834764831845f);
    }

    const int srow = tid >> 2;
    const int sg   = tid & 3;
    float mrun = -INFINITY, lrun = 0.f;

    float o[8][4];
    #pragma unroll
    for (int i = 0; i < 8; i++)
        #pragma unroll
        for (int j = 0; j < 4; j++) o[i][j] = 0.f;

    const int wm  = (wid & 3) * 16;
    const int wnk = (wid >> 2) * 32;
    const int wnv = (wid >> 2) * 64;
    const int rA0 = wm + lane/4, rA1 = rA0 + 8;

    const int njt = qt + 1;
    for (int jt = 0; jt < njt; jt++) {
        const int j0 = jt * 64;
        __syncthreads();
        #pragma unroll
        for (int i = 0; i < 8; i++) {
            int id = i*256 + tid;
            int rr = id >> 5, c4 = (id & 31) * 4;
            size_t base = (size_t)(bb*SS + j0 + rr) * QKVW + hh*HD + c4;
            float4 kv = *(const float4*)(qkv + base + HH*HD);
            float4 vv = *(const float4*)(qkv + base + 2*HH*HD);
            Ks[rr*132 + c4 + 0] = to_tf32(kv.x); Ks[rr*132 + c4 + 1] = to_tf32(kv.y);
            Ks[rr*132 + c4 + 2] = to_tf32(kv.z); Ks[rr*132 + c4 + 3] = to_tf32(kv.w);
            Vs[rr*132 + c4 + 0] = to_tf32(vv.x); Vs[rr*132 + c4 + 1] = to_tf32(vv.y);
            Vs[rr*132 + c4 + 2] = to_tf32(vv.z); Vs[rr*132 + c4 + 3] = to_tf32(vv.w);
        }
        __syncthreads();

        {
            float c[4][4];
            #pragma unroll
            for (int i = 0; i < 4; i++)
                #pragma unroll
                for (int j = 0; j < 4; j++) c[i][j] = 0.f;
            #pragma unroll
            for (int ks = 0; ks < 16; ks++) {
                const int k0 = ks*8 + (lane & 3);
                uint32_t a0 = __float_as_uint(Qs[rA0*132 + k0]);
                uint32_t a1 = __float_as_uint(Qs[rA1*132 + k0]);
                uint32_t a2 = __float_as_uint(Qs[rA0*132 + k0 + 4]);
                uint32_t a3 = __float_as_uint(Qs[rA1*132 + k0 + 4]);
                #pragma unroll
                for (int ntl = 0; ntl < 4; ntl++) {
                    const int nrow = wnk + ntl*8 + lane/4;
                    uint32_t b0 = __float_as_uint(Ks[nrow*132 + k0]);
                    uint32_t b1 = __float_as_uint(Ks[nrow*132 + k0 + 4]);
                    MMA1688TF(c[ntl], a0, a1, a2, a3, b0, b1);
                }
            }
            const int cc = (lane & 3) * 2;
            #pragma unroll
            for (int ntl = 0; ntl < 4; ntl++) {
                const int cb = wnk + ntl*8 + cc;
                Sb[rA0*68 + cb]     = c[ntl][0];
                Sb[rA0*68 + cb + 1] = c[ntl][1];
                Sb[rA1*68 + cb]     = c[ntl][2];
                Sb[rA1*68 + cb + 1] = c[ntl][3];
            }
        }
        __syncthreads();

        {
            const bool diag = (jt == qt);
            const int qi_rel = srow;
            float mx = -INFINITY;
            float pv[16];
            #pragma unroll
            for (int j = 0; j < 16; j++) {
                const int c = sg + 4*j;
                float v = Sb[srow*68 + c];
                if (diag && c > qi_rel) v = -INFINITY;
                pv[j] = v;
                mx = fmaxf(mx, v);
            }
            mx = fmaxf(mx, __shfl_xor_sync(0xffffffffu, mx, 1));
            mx = fmaxf(mx, __shfl_xor_sync(0xffffffffu, mx, 2));
            const float mNew = fmaxf(mrun, mx);
            const float corr = __expf(mrun - mNew);
            float ls = 0.f;
            #pragma unroll
            for (int j = 0; j < 16; j++) {
                const int c = sg + 4*j;
                float p = (pv[j] == -INFINITY) ? 0.f : to_tf32(__expf(pv[j] - mNew));
                Sb[srow*68 + c] = p;
                ls += p;
            }
            ls += __shfl_xor_sync(0xffffffffu, ls, 1);
            ls += __shfl_xor_sync(0xffffffffu, ls, 2);
            lrun = lrun * corr + ls;
            mrun = mNew;
            if (sg == 0) { Cr[srow] = corr; Ll[srow] = lrun; }
        }
        __syncthreads();

        {
            const float c0 = Cr[rA0], c1 = Cr[rA1];
            #pragma unroll
            for (int i = 0; i < 8; i++) {
                o[i][0] *= c0; o[i][1] *= c0;
                o[i][2] *= c1; o[i][3] *= c1;
            }
            #pragma unroll
            for (int ks = 0; ks < 8; ks++) {
                const int k0 = ks*8 + (lane & 3);
                uint32_t a0 = __float_as_uint(Sb[rA0*68 + k0]);
                uint32_t a1 = __float_as_uint(Sb[rA1*68 + k0]);
                uint32_t a2 = __float_as_uint(Sb[rA0*68 + k0 + 4]);
                uint32_t a3 = __float_as_uint(Sb[rA1*68 + k0 + 4]);
                #pragma unroll
                for (int ntl = 0; ntl < 8; ntl++) {
                    const int ncol = wnv + ntl*8 + lane/4;
                    uint32_t b0 = __float_as_uint(Vs[k0*132 + ncol]);
                    uint32_t b1 = __float_as_uint(Vs[(k0+4)*132 + ncol]);
                    MMA1688TF(o[ntl], a0, a1, a2, a3, b0, b1);
                }
            }
        }
    }
    __syncthreads();

    // ---- normalize + packed store (raw-reshape [B*S, D] row/col mapping)
    {
        const float inv0 = 1.f / Ll[rA0];
        const float inv1 = 1.f / Ll[rA1];
        const int t0 = (bb*HH + hh)*SS + q0 + rA0;
        const int t1 = (bb*HH + hh)*SS + q0 + rA1;
        const int m0 = t0 >> 4, cB0 = (t0 & 15) * 128;
        const int m1 = t1 >> 4, cB1 = (t1 & 15) * 128;
        const int cc = (lane & 3) * 2;
        #pragma unroll
        for (int ntl = 0; ntl < 8; ntl++) {
            const int cb = wnv + ntl*8 + cc;
            pack2A((char*)outP, DD/64, m0, cB0 + cb, o[ntl][0]*inv0, o[ntl][1]*inv0);
            pack2A((char*)outP, DD/64, m1, cB1 + cb, o[ntl][2]*inv1, o[ntl][3]*inv1);
        }
    }
}

// ---------------- launch --------------------------------------------------------
extern "C" void kernel_launch(void* const* d_in, const int* in_sizes, int n_in,
                              void* d_out, int out_size)
{
    (void)in_sizes; (void)n_in; (void)out_size;
    const float* x     = (const float*)d_in[0];
    const float* rms_w = (const float*)d_in[1];
    const float* w_qkv = (const float*)d_in[2];
    const float* w_out = (const float*)d_in[3];
    const float* w1    = (const float*)d_in[4];
    const float* b1    = (const float*)d_in[5];
    const float* w3    = (const float*)d_in[6];
    const float* b3    = (const float*)d_in[7];
    const float* w2    = (const float*)d_in[8];
    const float* b2    = (const float*)d_in[9];
    float* out = (float*)d_out;

    float *qkv, *a1;
    cudaGetSymbolAddress((void**)&qkv, g_qkv);
    cudaGetSymbolAddress((void**)&a1,  g_a1);
    __half *xn2,*att2,*h2,*gg2,*wqkv2,*wout2,*w12,*w32,*w22;
    cudaGetSymbolAddress((void**)&xn2,   g_xn2);
    cudaGetSymbolAddress((void**)&att2,  g_att2);
    cudaGetSymbolAddress((void**)&h2,    g_h2);
    cudaGetSymbolAddress((void**)&gg2,   g_gg2);
    cudaGetSymbolAddress((void**)&wqkv2, g_wqkv2);
    cudaGetSymbolAddress((void**)&wout2, g_wout2);
    cudaGetSymbolAddress((void**)&w12,   g_w12);
    cudaGetSymbolAddress((void**)&w32,   g_w32);
    cudaGetSymbolAddress((void**)&w22,   g_w22);

    cudaFuncSetAttribute(gemm_mma, cudaFuncAttributeMaxDynamicSharedMemorySize, G_SMEM);
    const int attn_smem = AT_SMEMF * (int)sizeof(float);
    cudaFuncSetAttribute(attn_tc, cudaFuncAttributeMaxDynamicSharedMemorySize, attn_smem);

    // weight conversions (hi-only, half the traffic of round 6)
    convW<<<(QKVW*DD/4 + 255)/256, 256>>>(w_qkv, wqkv2, DD, QKVW*DD/4);
    convW<<<(DD*DD/4   + 255)/256, 256>>>(w_out, wout2, DD, DD*DD/4);
    convW<<<(FF*DD/4   + 255)/256, 256>>>(w1,    w12,   DD, FF*DD/4);
    convW<<<(FF*DD/4   + 255)/256, 256>>>(w3,    w32,   DD, FF*DD/4);
    convW<<<(DD*FF/4   + 255)/256, 256>>>(w2,    w22,   FF, DD*FF/4);

    // 1) RMSNorm -> packed
    rmsnorm_pack<<<MM, 256>>>(x, rms_w, xn2);

    // 2) QKV projection (fp32 out for attention)
    gemm_mma<<<dim3(QKVW/128, MM/128), 288, G_SMEM>>>(
        xn2, wqkv2, nullptr, nullptr, qkv, nullptr, QKVW, DD/64, 0);

    // 3) attention -> packed att2
    attn_tc<<<dim3(SS/64, HH, BB), 256, attn_smem>>>(qkv, att2);

    // 4) out projection -> packed h2
    gemm_mma<<<dim3(DD/128, MM/128), 288, G_SMEM>>>(
        att2, wout2, nullptr, nullptr, nullptr, h2, DD, DD/64, 0);

    // 5) a1 = h @ w1^T + b1 (fp32, consumed as E)
    gemm_mma<<<dim3(FF/128, MM/128), 288, G_SMEM>>>(
        h2, w12, b1, nullptr, a1, nullptr, FF, DD/64, 0);

    // 6) gg = a1 + relu(h @ w3^T + b3) -> packed gg2
    gemm_mma<<<dim3(FF/128, MM/128), 288, G_SMEM>>>(
        h2, w32, b3, a1, nullptr, gg2, FF, DD/64, 1);

    // 7) out = x + gg @ w2^T + b2 (fp32 final)
    gemm_mma<<<dim3(DD/128, MM/128), 288, G_SMEM>>>(
        gg2, w22, b2, x, out, nullptr, DD, FF/64, 2);
}

// round 8
// speedup vs baseline: 1.5843x; 1.5843x over previous
#include <cuda_runtime.h>
#include <cuda_fp16.h>
#include <math.h>
#include <stdint.h>

#define BB   2
#define SS   2048
#define DD   2048
#define HH   16
#define HD   128
#define FF   8192
#define MM   (BB*SS)          // 4096
#define QKVW (3*DD)           // 6144

// ---------------- fp32 scratch ----------------
__device__ float g_qkv[MM*QKVW];
__device__ float g_a1 [MM*FF];

// ---------------- fp16 packed scratch (all hi-only, [rows/128][K/64][128][64], SW128)
__device__ __half g_xn2 [(size_t)MM*DD];
__device__ __half g_att2[(size_t)MM*DD];
__device__ __half g_h2  [(size_t)MM*DD];
__device__ __half g_gg2 [(size_t)MM*FF];
__device__ __half g_wqkv2[(size_t)QKVW*DD];
__device__ __half g_wout2[(size_t)DD*DD];
__device__ __half g_w12 [(size_t)FF*DD];
__device__ __half g_w32 [(size_t)FF*DD];
__device__ __half g_w22 [(size_t)DD*FF];

// ---------------- PTX helpers -------------------------------------------------
__device__ __forceinline__ uint32_t smem_u32(const void* p) {
    uint32_t a;
    asm("{ .reg .u64 t; cvta.to.shared.u64 t, %1; cvt.u32.u64 %0, t; }" : "=r"(a) : "l"(p));
    return a;
}
__device__ __forceinline__ uint32_t elect_one() {
    uint32_t p;
    asm volatile("{ .reg .pred p; elect.sync _|p, 0xFFFFFFFF; selp.b32 %0,1,0,p; }" : "=r"(p));
    return p;
}
__device__ __forceinline__ float to_tf32(float x) {
    uint32_t t;
    asm("cvt.rna.tf32.f32 %0, %1;" : "=r"(t) : "f"(x));
    return __uint_as_float(t);
}
#define MBAR_INIT(a, c) \
    asm volatile("mbarrier.init.shared.b64 [%0], %1;" :: "r"(a), "r"(c) : "memory")
#define MBAR_EXPECT(a, b) \
    asm volatile("mbarrier.arrive.expect_tx.shared.b64 _, [%0], %1;" :: "r"(a), "r"(b) : "memory")
#define MBAR_ARRIVE(a) \
    asm volatile("mbarrier.arrive.shared.b64 _, [%0];" :: "r"(a) : "memory")
#define MBAR_WAIT(a, ph) do { uint32_t _m=(a), _p=(ph), _d;                                   \
    asm volatile("{ .reg .pred p; mbarrier.try_wait.parity.acquire.cta.shared::cta.b64 p, [%1], %2; selp.b32 %0,1,0,p; }" \
                 : "=r"(_d) : "r"(_m), "r"(_p) : "memory");                                   \
    if (!_d) {                                                                                \
      asm volatile("{ .reg .pred P1; WL%=: mbarrier.try_wait.parity.acquire.cta.shared::cta.b64 P1, [%0], %1, 0x989680; @P1 bra.uni WD%=; bra.uni WL%=; WD%=: }" \
                   :: "r"(_m), "r"(_p) : "memory"); } } while(0)
#define BULK_G2S(d, s, n, m) \
    asm volatile("cp.async.bulk.shared::cta.global.mbarrier::complete_tx::bytes [%0], [%1], %2, [%3];" \
                 :: "r"(d), "l"(s), "r"(n), "r"(m) : "memory")
#define LDSM_X4(r0, r1, r2, r3, a) \
    asm volatile("ldmatrix.sync.aligned.m8n8.x4.shared.b16 {%0,%1,%2,%3}, [%4];" \
                 : "=r"(r0), "=r"(r1), "=r"(r2), "=r"(r3) : "r"(a))
#define MMA16816H(d, av, bv) \
    asm volatile("mma.sync.aligned.m16n8k16.row.col.f32.f16.f16.f32 " \
                 "{%0,%1,%2,%3}, {%4,%5,%6,%7}, {%8,%9}, {%0,%1,%2,%3};" \
                 : "+f"((d)[0]), "+f"((d)[1]), "+f"((d)[2]), "+f"((d)[3]) \
                 : "r"((av)[0]), "r"((av)[1]), "r"((av)[2]), "r"((av)[3]), \
                   "r"((bv)[0]), "r"((bv)[1]))
#define MMA1688TF(d, a0, a1, a2, a3, b0, b1) \
    asm volatile("mma.sync.aligned.m16n8k8.row.col.f32.tf32.tf32.f32 " \
                 "{%0,%1,%2,%3}, {%4,%5,%6,%7}, {%8,%9}, {%0,%1,%2,%3};" \
                 : "+f"((d)[0]), "+f"((d)[1]), "+f"((d)[2]), "+f"((d)[3]) \
                 : "r"(a0), "r"(a1), "r"(a2), "r"(a3), "r"(b0), "r"(b1))

// ---------------- fp16 hi-only pack helpers -----------------------------------
__device__ __forceinline__ uint32_t h2pack(float v0, float v1) {
    return (uint32_t)__half_as_ushort(__float2half_rn(v0))
         | ((uint32_t)__half_as_ushort(__float2half_rn(v1)) << 16);
}
__device__ __forceinline__ void pack4H(char* base, int ktK, int m, int n, float4 v) {
    const int mt = m >> 7, mr = m & 127;
    const int kt = n >> 6, c = n & 63;
    const size_t tb = ((size_t)mt * ktK + kt) * 16384;
    uint32_t off = (uint32_t)(mr * 128 + c * 2);
    off ^= (off >> 3) & 0x70;
    *(uint2*)(base + tb + off) = make_uint2(h2pack(v.x, v.y), h2pack(v.z, v.w));
}
__device__ __forceinline__ void pack2H(char* base, int ktK, int m, int n, float v0, float v1) {
    const int mt = m >> 7, mr = m & 127;
    const int kt = n >> 6, c = n & 63;
    const size_t tb = ((size_t)mt * ktK + kt) * 16384;
    uint32_t off = (uint32_t)(mr * 128 + c * 2);
    off ^= (off >> 3) & 0x70;
    *(uint32_t*)(base + tb + off) = h2pack(v0, v1);
}

// ---------------- RMSNorm -> packed fp16 --------------------------------------
__global__ __launch_bounds__(256) void rmsnorm_pack(
    const float* __restrict__ x, const float* __restrict__ w, __half* __restrict__ dst)
{
    const int row = blockIdx.x;
    const float4* xr = (const float4*)(x + (size_t)row * DD);
    float4 a = xr[threadIdx.x];
    float4 b = xr[threadIdx.x + 256];
    float ss = a.x*a.x + a.y*a.y + a.z*a.z + a.w*a.w
             + b.x*b.x + b.y*b.y + b.z*b.z + b.w*b.w;
    #pragma unroll
    for (int o = 16; o; o >>= 1) ss += __shfl_xor_sync(0xffffffffu, ss, o);
    __shared__ float sred[8];
    if ((threadIdx.x & 31) == 0) sred[threadIdx.x >> 5] = ss;
    __syncthreads();
    float tot = sred[0]+sred[1]+sred[2]+sred[3]+sred[4]+sred[5]+sred[6]+sred[7];
    float sc = rsqrtf(tot * (1.0f / DD) + 1e-5f);

    const float4* wr = (const float4*)w;
    #pragma unroll
    for (int g = 0; g < 2; g++) {
        const int gi = threadIdx.x + g*256;
        float4 v = (g == 0) ? a : b;
        float4 wv = wr[gi];
        v.x *= sc * wv.x; v.y *= sc * wv.y; v.z *= sc * wv.z; v.w *= sc * wv.w;
        pack4H((char*)dst, DD/64, row, gi*4, v);
    }
}

// ---------------- weight fp32 -> fp16 hi-only tile-packed ---------------------
__global__ __launch_bounds__(256) void convW(
    const float* __restrict__ src, __half* __restrict__ dst, int K, int total4)
{
    int gid = blockIdx.x * 256 + threadIdx.x;
    if (gid >= total4) return;
    const int kq = K >> 2;
    const int m  = gid / kq;
    const int k  = (gid - m * kq) << 2;
    float4 v = *(const float4*)(src + (size_t)m * K + k);
    pack4H((char*)dst, K >> 6, m, k, v);
}

// ---------------- fp16 mma.sync GEMM: C = A(hi)·B(hi)^T -----------------------
// both operands [rt/128][K/64][128][64] packed. 128x128 tile, 8 math warps + producer.
// out: P!=null -> packed fp16 ; else fp32 C.
// mode 0: v(+bias) ; mode 1: E + relu(v+bias) ; mode 2: E + v + bias
#define G_STG    4
#define G_TB     16384
#define G_SMEM   (1024 + G_STG*2*G_TB)        // 132096
#define GROUP_M  8

__global__ __launch_bounds__(288, 1) void gemm_mma(
    const __half* __restrict__ A2, const __half* __restrict__ B2,
    const float* __restrict__ bias, const float* __restrict__ E,
    float* __restrict__ C, __half* __restrict__ P,
    int N, int ktK, int mode)
{
    extern __shared__ char sm[];
    const uint32_t sb = smem_u32(sm);
    const int tid = threadIdx.x, wid = tid >> 5, lane = tid & 31;

    const uint32_t MFULL  = sb;
    const uint32_t MEMPTY = sb + 256;
    const uint32_t SA     = sb + 1024;
    const uint32_t SBq    = SA + G_STG * G_TB;

    if (tid == 0) {
        #pragma unroll
        for (int s = 0; s < G_STG; s++) { MBAR_INIT(MFULL + s*8, 1); MBAR_INIT(MEMPTY + s*8, 8); }
    }
    __syncthreads();

    const int gridN = gridDim.x;
    const int bid   = blockIdx.y * gridN + blockIdx.x;
    const int tpg   = GROUP_M * gridN;
    const int grp   = bid / tpg, rem = bid - grp * tpg;
    const int mt    = grp * GROUP_M + (rem % GROUP_M);
    const int nt    = rem / GROUP_M;

    float d[2][8][4];
    #pragma unroll
    for (int a = 0; a < 2; a++)
        #pragma unroll
        for (int b = 0; b < 8; b++)
            #pragma unroll
            for (int c = 0; c < 4; c++) d[a][b][c] = 0.f;

    if (wid == 8) {
        if (elect_one()) {
            const char* Ag = (const char*)A2 + (size_t)mt * ktK * G_TB;
            const char* Bg = (const char*)B2 + (size_t)nt * ktK * G_TB;
            int s = 0, ph = 1;
            for (int kt = 0; kt < ktK; kt++) {
                MBAR_WAIT(MEMPTY + s*8, ph);
                MBAR_EXPECT(MFULL + s*8, 2*G_TB);
                BULK_G2S(SA  + s*G_TB, Ag + (size_t)kt*G_TB, G_TB, MFULL + s*8);
                BULK_G2S(SBq + s*G_TB, Bg + (size_t)kt*G_TB, G_TB, MFULL + s*8);
                if (++s == G_STG) { s = 0; ph ^= 1; }
            }
        }
    } else {
        const int wm = (wid & 3) * 32;
        const int wn = (wid >> 2) * 64;
        const uint32_t rsub   = (uint32_t)(((lane >> 3) & 1) * 8 + (lane & 7));
        const uint32_t ksel   = (uint32_t)((lane >> 4) * 16);
        const uint32_t cmask  = (uint32_t)((lane & 7) << 4);
        const uint32_t aRowOff = (uint32_t)(wm + rsub) * 128;
        const uint32_t bRowOff = (uint32_t)(wn + rsub) * 128;

        int s = 0, ph = 0;
        for (int kt = 0; kt < ktK; kt++) {
            MBAR_WAIT(MFULL + s*8, ph);
            const uint32_t sa  = SA  + s*G_TB;
            const uint32_t sbb = SBq + s*G_TB;
            #pragma unroll
            for (int kk4 = 0; kk4 < 4; kk4++) {
                const uint32_t ko = (uint32_t)(kk4*32 + ksel) ^ cmask;
                uint32_t af[2][4];
                #pragma unroll
                for (int mi = 0; mi < 2; mi++)
                    LDSM_X4(af[mi][0], af[mi][1], af[mi][2], af[mi][3],
                            sa + aRowOff + mi*2048 + ko);
                uint32_t bf[8][2];
                #pragma unroll
                for (int ng = 0; ng < 4; ng++) {
                    uint32_t t0, t1, t2, t3;
                    LDSM_X4(t0, t1, t2, t3, sbb + bRowOff + ng*2048 + ko);
                    bf[2*ng][0] = t0; bf[2*ng+1][0] = t1;
                    bf[2*ng][1] = t2; bf[2*ng+1][1] = t3;
                }
                #pragma unroll
                for (int mi = 0; mi < 2; mi++)
                    #pragma unroll
                    for (int ni = 0; ni < 8; ni++)
                        MMA16816H(d[mi][ni], af[mi], bf[ni]);
            }
            if (lane == 0) MBAR_ARRIVE(MEMPTY + s*8);
            if (++s == G_STG) { s = 0; ph ^= 1; }
        }
    }

    __syncthreads();

    float* st = (float*)(sm + 1024);
    if (wid < 8) {
        const int wm = (wid & 3) * 32;
        const int wn = (wid >> 2) * 64;
        const int r0 = lane >> 2;
        const int cc = (lane & 3) * 2;
        #pragma unroll
        for (int mi = 0; mi < 2; mi++)
            #pragma unroll
            for (int ni = 0; ni < 8; ni++) {
                const int r = wm + mi*16 + r0;
                const int c = wn + ni*8 + cc;
                st[r*132 + c]       = d[mi][ni][0];
                st[r*132 + c + 1]   = d[mi][ni][1];
                st[(r+8)*132 + c]   = d[mi][ni][2];
                st[(r+8)*132 + c+1] = d[mi][ni][3];
            }
    }
    __syncthreads();

    if (tid < 256) {
        const int r0 = tid >> 5;
        const int c  = (tid & 31) * 4;
        const int n  = nt*128 + c;
        float4 bv = make_float4(0.f, 0.f, 0.f, 0.f);
        if (bias) bv = *(const float4*)(bias + n);
        #pragma unroll 4
        for (int rp = 0; rp < 16; rp++) {
            const int r = rp*8 + r0;
            const size_t idx = (size_t)(mt*128 + r) * N + n;
            float4 v = *(float4*)&st[r*132 + c];
            v.x += bv.x; v.y += bv.y; v.z += bv.z; v.w += bv.w;
            if (mode == 1) {
                float4 e = *(const float4*)(E + idx);
                v.x = e.x + fmaxf(v.x, 0.f); v.y = e.y + fmaxf(v.y, 0.f);
                v.z = e.z + fmaxf(v.z, 0.f); v.w = e.w + fmaxf(v.w, 0.f);
            } else if (mode == 2) {
                float4 e = *(const float4*)(E + idx);
                v.x += e.x; v.y += e.y; v.z += e.z; v.w += e.w;
            }
            if (P) pack4H((char*)P, N >> 6, mt*128 + r, n, v);
            else   *(float4*)(C + idx) = v;
        }
    }
}

// ---------------- tf32 tensor-core causal flash attention -> packed -----------
#define AT_SMEMF (3*64*132 + 64*68 + 128)
__global__ __launch_bounds__(256) void attn_tc(
    const float* __restrict__ qkv, __half* __restrict__ outP)
{
    extern __shared__ float s[];
    float* Qs = s;
    float* Ks = Qs + 64*132;
    float* Vs = Ks + 64*132;
    float* Sb = Vs + 64*132;
    float* Cr = Sb + 64*68;
    float* Ll = Cr + 64;

    const int tid = threadIdx.x, wid = tid >> 5, lane = tid & 31;
    const int qt = blockIdx.x, hh = blockIdx.y, bb = blockIdx.z;
    const int q0 = qt * 64;

    #pragma unroll
    for (int i = 0; i < 8; i++) {
        int id = i*256 + tid;
        int rr = id >> 5, c4 = (id & 31) * 4;
        float4 v = *(const float4*)(qkv + (size_t)(bb*SS + q0 + rr) * QKVW + hh*HD + c4);
        Qs[rr*132 + c4 + 0] = to_tf32(v.x * 0.08838834764831845f);
        Qs[rr*132 + c4 + 1] = to_tf32(v.y * 0.08838834764831845f);
        Qs[rr*132 + c4 + 2] = to_tf32(v.z * 0.08838834764831845f);
        Qs[rr*132 + c4 + 3] = to_tf32(v.w * 0.08838834764831845f);
    }

    const int srow = tid >> 2;
    const int sg   = tid & 3;
    float mrun = -INFINITY, lrun = 0.f;

    float o[8][4];
    #pragma unroll
    for (int i = 0; i < 8; i++)
        #pragma unroll
        for (int j = 0; j < 4; j++) o[i][j] = 0.f;

    const int wm  = (wid & 3) * 16;
    const int wnk = (wid >> 2) * 32;
    const int wnv = (wid >> 2) * 64;
    const int rA0 = wm + lane/4, rA1 = rA0 + 8;

    const int njt = qt + 1;
    for (int jt = 0; jt < njt; jt++) {
        const int j0 = jt * 64;
        __syncthreads();
        #pragma unroll
        for (int i = 0; i < 8; i++) {
            int id = i*256 + tid;
            int rr = id >> 5, c4 = (id & 31) * 4;
            size_t base = (size_t)(bb*SS + j0 + rr) * QKVW + hh*HD + c4;
            float4 kv = *(const float4*)(qkv + base + HH*HD);
            float4 vv = *(const float4*)(qkv + base + 2*HH*HD);
            Ks[rr*132 + c4 + 0] = to_tf32(kv.x); Ks[rr*132 + c4 + 1] = to_tf32(kv.y);
            Ks[rr*132 + c4 + 2] = to_tf32(kv.z); Ks[rr*132 + c4 + 3] = to_tf32(kv.w);
            Vs[rr*132 + c4 + 0] = to_tf32(vv.x); Vs[rr*132 + c4 + 1] = to_tf32(vv.y);
            Vs[rr*132 + c4 + 2] = to_tf32(vv.z); Vs[rr*132 + c4 + 3] = to_tf32(vv.w);
        }
        __syncthreads();

        {
            float c[4][4];
            #pragma unroll
            for (int i = 0; i < 4; i++)
                #pragma unroll
                for (int j = 0; j < 4; j++) c[i][j] = 0.f;
            #pragma unroll
            for (int ks = 0; ks < 16; ks++) {
                const int k0 = ks*8 + (lane & 3);
                uint32_t a0 = __float_as_uint(Qs[rA0*132 + k0]);
                uint32_t a1 = __float_as_uint(Qs[rA1*132 + k0]);
                uint32_t a2 = __float_as_uint(Qs[rA0*132 + k0 + 4]);
                uint32_t a3 = __float_as_uint(Qs[rA1*132 + k0 + 4]);
                #pragma unroll
                for (int ntl = 0; ntl < 4; ntl++) {
                    const int nrow = wnk + ntl*8 + lane/4;
                    uint32_t b0 = __float_as_uint(Ks[nrow*132 + k0]);
                    uint32_t b1 = __float_as_uint(Ks[nrow*132 + k0 + 4]);
                    MMA1688TF(c[ntl], a0, a1, a2, a3, b0, b1);
                }
            }
            const int cc = (lane & 3) * 2;
            #pragma unroll
            for (int ntl = 0; ntl < 4; ntl++) {
                const int cb = wnk + ntl*8 + cc;
                Sb[rA0*68 + cb]     = c[ntl][0];
                Sb[rA0*68 + cb + 1] = c[ntl][1];
                Sb[rA1*68 + cb]     = c[ntl][2];
                Sb[rA1*68 + cb + 1] = c[ntl][3];
            }
        }
        __syncthreads();

        {
            const bool diag = (jt == qt);
            const int qi_rel = srow;
            float mx = -INFINITY;
            float pv[16];
            #pragma unroll
            for (int j = 0; j < 16; j++) {
                const int c = sg + 4*j;
                float v = Sb[srow*68 + c];
                if (diag && c > qi_rel) v = -INFINITY;
                pv[j] = v;
                mx = fmaxf(mx, v);
            }
            mx = fmaxf(mx, __shfl_xor_sync(0xffffffffu, mx, 1));
            mx = fmaxf(mx, __shfl_xor_sync(0xffffffffu, mx, 2));
            const float mNew = fmaxf(mrun, mx);
            const float corr = __expf(mrun - mNew);
            float ls = 0.f;
            #pragma unroll
            for (int j = 0; j < 16; j++) {
                const int c = sg + 4*j;
                float p = (pv[j] == -INFINITY) ? 0.f : to_tf32(__expf(pv[j] - mNew));
                Sb[srow*68 + c] = p;
                ls += p;
            }
            ls += __shfl_xor_sync(0xffffffffu, ls, 1);
            ls += __shfl_xor_sync(0xffffffffu, ls, 2);
            lrun = lrun * corr + ls;
            mrun = mNew;
            if (sg == 0) { Cr[srow] = corr; Ll[srow] = lrun; }
        }
        __syncthreads();

        {
            const float c0 = Cr[rA0], c1 = Cr[rA1];
            #pragma unroll
            for (int i = 0; i < 8; i++) {
                o[i][0] *= c0; o[i][1] *= c0;
                o[i][2] *= c1; o[i][3] *= c1;
            }
            #pragma unroll
            for (int ks = 0; ks < 8; ks++) {
                const int k0 = ks*8 + (lane & 3);
                uint32_t a0 = __float_as_uint(Sb[rA0*68 + k0]);
                uint32_t a1 = __float_as_uint(Sb[rA1*68 + k0]);
                uint32_t a2 = __float_as_uint(Sb[rA0*68 + k0 + 4]);
                uint32_t a3 = __float_as_uint(Sb[rA1*68 + k0 + 4]);
                #pragma unroll
                for (int ntl = 0; ntl < 8; ntl++) {
                    const int ncol = wnv + ntl*8 + lane/4;
                    uint32_t b0 = __float_as_uint(Vs[k0*132 + ncol]);
                    uint32_t b1 = __float_as_uint(Vs[(k0+4)*132 + ncol]);
                    MMA1688TF(o[ntl], a0, a1, a2, a3, b0, b1);
                }
            }
        }
    }
    __syncthreads();

    {
        const float inv0 = 1.f / Ll[rA0];
        const float inv1 = 1.f / Ll[rA1];
        const int t0 = (bb*HH + hh)*SS + q0 + rA0;
        const int t1 = (bb*HH + hh)*SS + q0 + rA1;
        const int m0 = t0 >> 4, cB0 = (t0 & 15) * 128;
        const int m1 = t1 >> 4, cB1 = (t1 & 15) * 128;
        const int cc = (lane & 3) * 2;
        #pragma unroll
        for (int ntl = 0; ntl < 8; ntl++) {
            const int cb = wnv + ntl*8 + cc;
            pack2H((char*)outP, DD/64, m0, cB0 + cb, o[ntl][0]*inv0, o[ntl][1]*inv0);
            pack2H((char*)outP, DD/64, m1, cB1 + cb, o[ntl][2]*inv1, o[ntl][3]*inv1);
        }
    }
}

// ---------------- launch --------------------------------------------------------
extern "C" void kernel_launch(void* const* d_in, const int* in_sizes, int n_in,
                              void* d_out, int out_size)
{
    (void)in_sizes; (void)n_in; (void)out_size;
    const float* x     = (const float*)d_in[0];
    const float* rms_w = (const float*)d_in[1];
    const float* w_qkv = (const float*)d_in[2];
    const float* w_out = (const float*)d_in[3];
    const float* w1    = (const float*)d_in[4];
    const float* b1    = (const float*)d_in[5];
    const float* w3    = (const float*)d_in[6];
    const float* b3    = (const float*)d_in[7];
    const float* w2    = (const float*)d_in[8];
    const float* b2    = (const float*)d_in[9];
    float* out = (float*)d_out;

    float *qkv, *a1;
    cudaGetSymbolAddress((void**)&qkv, g_qkv);
    cudaGetSymbolAddress((void**)&a1,  g_a1);
    __half *xn2,*att2,*h2,*gg2,*wqkv2,*wout2,*w12,*w32,*w22;
    cudaGetSymbolAddress((void**)&xn2,   g_xn2);
    cudaGetSymbolAddress((void**)&att2,  g_att2);
    cudaGetSymbolAddress((void**)&h2,    g_h2);
    cudaGetSymbolAddress((void**)&gg2,   g_gg2);
    cudaGetSymbolAddress((void**)&wqkv2, g_wqkv2);
    cudaGetSymbolAddress((void**)&wout2, g_wout2);
    cudaGetSymbolAddress((void**)&w12,   g_w12);
    cudaGetSymbolAddress((void**)&w32,   g_w32);
    cudaGetSymbolAddress((void**)&w22,   g_w22);

    cudaFuncSetAttribute(gemm_mma, cudaFuncAttributeMaxDynamicSharedMemorySize, G_SMEM);
    const int attn_smem = AT_SMEMF * (int)sizeof(float);
    cudaFuncSetAttribute(attn_tc, cudaFuncAttributeMaxDynamicSharedMemorySize, attn_smem);

    // weight conversions (hi-only)
    convW<<<(QKVW*DD/4 + 255)/256, 256>>>(w_qkv, wqkv2, DD, QKVW*DD/4);
    convW<<<(DD*DD/4   + 255)/256, 256>>>(w_out, wout2, DD, DD*DD/4);
    convW<<<(FF*DD/4   + 255)/256, 256>>>(w1,    w12,   DD, FF*DD/4);
    convW<<<(FF*DD/4   + 255)/256, 256>>>(w3,    w32,   DD, FF*DD/4);
    convW<<<(DD*FF/4   + 255)/256, 256>>>(w2,    w22,   FF, DD*FF/4);

    // 1) RMSNorm -> packed
    rmsnorm_pack<<<MM, 256>>>(x, rms_w, xn2);

    // 2) QKV projection (fp32 out for attention)
    gemm_mma<<<dim3(QKVW/128, MM/128), 288, G_SMEM>>>(
        xn2, wqkv2, nullptr, nullptr, qkv, nullptr, QKVW, DD/64, 0);

    // 3) attention -> packed att2
    attn_tc<<<dim3(SS/64, HH, BB), 256, attn_smem>>>(qkv, att2);

    // 4) out projection -> packed h2
    gemm_mma<<<dim3(DD/128, MM/128), 288, G_SMEM>>>(
        att2, wout2, nullptr, nullptr, nullptr, h2, DD, DD/64, 0);

    // 5) a1 = h @ w1^T + b1 (fp32, consumed as E)
    gemm_mma<<<dim3(FF/128, MM/128), 288, G_SMEM>>>(
        h2, w12, b1, nullptr, a1, nullptr, FF, DD/64, 0);

    // 6) gg = a1 + relu(h @ w3^T + b3) -> packed gg2
    gemm_mma<<<dim3(FF/128, MM/128), 288, G_SMEM>>>(
        h2, w32, b3, a1, nullptr, gg2, FF, DD/64, 1);

    // 7) out = x + gg @ w2^T + b2 (fp32 final)
    gemm_mma<<<dim3(DD/128, MM/128), 288, G_SMEM>>>(
        gg2, w22, b2, x, out, nullptr, DD, FF/64, 2);
}

// round 9
// speedup vs baseline: 1.7523x; 1.1060x over previous
#include <cuda_runtime.h>
#include <cuda_fp16.h>
#include <math.h>
#include <stdint.h>

#define BB   2
#define SS   2048
#define DD   2048
#define HH   16
#define HD   128
#define FF   8192
#define MM   (BB*SS)          // 4096
#define QKVW (3*DD)           // 6144

// ---------------- fp32 scratch ----------------
__device__ float g_qkv[MM*QKVW];
__device__ float g_a1 [MM*FF];

// ---------------- fp16 packed scratch (all hi-only, [rows/128][K/64][128][64], SW128)
__device__ __half g_xn2 [(size_t)MM*DD];
__device__ __half g_att2[(size_t)MM*DD];
__device__ __half g_h2  [(size_t)MM*DD];
__device__ __half g_gg2 [(size_t)MM*FF];
__device__ __half g_wqkv2[(size_t)QKVW*DD];
__device__ __half g_wout2[(size_t)DD*DD];
__device__ __half g_w12 [(size_t)FF*DD];
__device__ __half g_w32 [(size_t)FF*DD];
__device__ __half g_w22 [(size_t)DD*FF];

// ---------------- PTX helpers -------------------------------------------------
__device__ __forceinline__ uint32_t smem_u32(const void* p) {
    uint32_t a;
    asm("{ .reg .u64 t; cvta.to.shared.u64 t, %1; cvt.u32.u64 %0, t; }" : "=r"(a) : "l"(p));
    return a;
}
__device__ __forceinline__ uint32_t elect_one() {
    uint32_t p;
    asm volatile("{ .reg .pred p; elect.sync _|p, 0xFFFFFFFF; selp.b32 %0,1,0,p; }" : "=r"(p));
    return p;
}
__device__ __forceinline__ float to_tf32(float x) {
    uint32_t t;
    asm("cvt.rna.tf32.f32 %0, %1;" : "=r"(t) : "f"(x));
    return __uint_as_float(t);
}
#define MBAR_INIT(a, c) \
    asm volatile("mbarrier.init.shared.b64 [%0], %1;" :: "r"(a), "r"(c) : "memory")
#define MBAR_EXPECT(a, b) \
    asm volatile("mbarrier.arrive.expect_tx.shared.b64 _, [%0], %1;" :: "r"(a), "r"(b) : "memory")
#define MBAR_ARRIVE(a) \
    asm volatile("mbarrier.arrive.shared.b64 _, [%0];" :: "r"(a) : "memory")
#define MBAR_WAIT(a, ph) do { uint32_t _m=(a), _p=(ph), _d;                                   \
    asm volatile("{ .reg .pred p; mbarrier.try_wait.parity.acquire.cta.shared::cta.b64 p, [%1], %2; selp.b32 %0,1,0,p; }" \
                 : "=r"(_d) : "r"(_m), "r"(_p) : "memory");                                   \
    if (!_d) {                                                                                \
      asm volatile("{ .reg .pred P1; WL%=: mbarrier.try_wait.parity.acquire.cta.shared::cta.b64 P1, [%0], %1, 0x989680; @P1 bra.uni WD%=; bra.uni WL%=; WD%=: }" \
                   :: "r"(_m), "r"(_p) : "memory"); } } while(0)
#define BULK_G2S(d, s, n, m) \
    asm volatile("cp.async.bulk.shared::cta.global.mbarrier::complete_tx::bytes [%0], [%1], %2, [%3];" \
                 :: "r"(d), "l"(s), "r"(n), "r"(m) : "memory")
#define LDSM_X4(r0, r1, r2, r3, a) \
    asm volatile("ldmatrix.sync.aligned.m8n8.x4.shared.b16 {%0,%1,%2,%3}, [%4];" \
                 : "=r"(r0), "=r"(r1), "=r"(r2), "=r"(r3) : "r"(a))
#define MMA16816H(d, av, bv) \
    asm volatile("mma.sync.aligned.m16n8k16.row.col.f32.f16.f16.f32 " \
                 "{%0,%1,%2,%3}, {%4,%5,%6,%7}, {%8,%9}, {%0,%1,%2,%3};" \
                 : "+f"((d)[0]), "+f"((d)[1]), "+f"((d)[2]), "+f"((d)[3]) \
                 : "r"((av)[0]), "r"((av)[1]), "r"((av)[2]), "r"((av)[3]), \
                   "r"((bv)[0]), "r"((bv)[1]))
#define MMA1688TF(d, a0, a1, a2, a3, b0, b1) \
    asm volatile("mma.sync.aligned.m16n8k8.row.col.f32.tf32.tf32.f32 " \
                 "{%0,%1,%2,%3}, {%4,%5,%6,%7}, {%8,%9}, {%0,%1,%2,%3};" \
                 : "+f"((d)[0]), "+f"((d)[1]), "+f"((d)[2]), "+f"((d)[3]) \
                 : "r"(a0), "r"(a1), "r"(a2), "r"(a3), "r"(b0), "r"(b1))

// ---------------- fp16 hi-only pack helpers -----------------------------------
__device__ __forceinline__ uint32_t h2pack(float v0, float v1) {
    return (uint32_t)__half_as_ushort(__float2half_rn(v0))
         | ((uint32_t)__half_as_ushort(__float2half_rn(v1)) << 16);
}
__device__ __forceinline__ void pack4H(char* base, int ktK, int m, int n, float4 v) {
    const int mt = m >> 7, mr = m & 127;
    const int kt = n >> 6, c = n & 63;
    const size_t tb = ((size_t)mt * ktK + kt) * 16384;
    uint32_t off = (uint32_t)(mr * 128 + c * 2);
    off ^= (off >> 3) & 0x70;
    *(uint2*)(base + tb + off) = make_uint2(h2pack(v.x, v.y), h2pack(v.z, v.w));
}
__device__ __forceinline__ void pack2H(char* base, int ktK, int m, int n, float v0, float v1) {
    const int mt = m >> 7, mr = m & 127;
    const int kt = n >> 6, c = n & 63;
    const size_t tb = ((size_t)mt * ktK + kt) * 16384;
    uint32_t off = (uint32_t)(mr * 128 + c * 2);
    off ^= (off >> 3) & 0x70;
    *(uint32_t*)(base + tb + off) = h2pack(v0, v1);
}

// ---------------- RMSNorm -> packed fp16 --------------------------------------
__global__ __launch_bounds__(256) void rmsnorm_pack(
    const float* __restrict__ x, const float* __restrict__ w, __half* __restrict__ dst)
{
    const int row = blockIdx.x;
    const float4* xr = (const float4*)(x + (size_t)row * DD);
    float4 a = xr[threadIdx.x];
    float4 b = xr[threadIdx.x + 256];
    float ss = a.x*a.x + a.y*a.y + a.z*a.z + a.w*a.w
             + b.x*b.x + b.y*b.y + b.z*b.z + b.w*b.w;
    #pragma unroll
    for (int o = 16; o; o >>= 1) ss += __shfl_xor_sync(0xffffffffu, ss, o);
    __shared__ float sred[8];
    if ((threadIdx.x & 31) == 0) sred[threadIdx.x >> 5] = ss;
    __syncthreads();
    float tot = sred[0]+sred[1]+sred[2]+sred[3]+sred[4]+sred[5]+sred[6]+sred[7];
    float sc = rsqrtf(tot * (1.0f / DD) + 1e-5f);

    const float4* wr = (const float4*)w;
    #pragma unroll
    for (int g = 0; g < 2; g++) {
        const int gi = threadIdx.x + g*256;
        float4 v = (g == 0) ? a : b;
        float4 wv = wr[gi];
        v.x *= sc * wv.x; v.y *= sc * wv.y; v.z *= sc * wv.z; v.w *= sc * wv.w;
        pack4H((char*)dst, DD/64, row, gi*4, v);
    }
}

// ---------------- weight fp32 -> fp16 hi-only tile-packed ---------------------
__global__ __launch_bounds__(256) void convW(
    const float* __restrict__ src, __half* __restrict__ dst, int K, int total4)
{
    int gid = blockIdx.x * 256 + threadIdx.x;
    if (gid >= total4) return;
    const int kq = K >> 2;
    const int m  = gid / kq;
    const int k  = (gid - m * kq) << 2;
    float4 v = *(const float4*)(src + (size_t)m * K + k);
    pack4H((char*)dst, K >> 6, m, k, v);
}

// ---------------- fp16 mma.sync GEMM: C = A(hi)·B(hi)^T -----------------------
// 128x128 tile, 8 math warps + producer; 3 stages; 2 CTAs/SM.
#define G_STG    3
#define G_TB     16384
#define G_SMEM   (1024 + G_STG*2*G_TB)        // 99328
#define GROUP_M  8

__global__ __launch_bounds__(288, 2) void gemm_mma(
    const __half* __restrict__ A2, const __half* __restrict__ B2,
    const float* __restrict__ bias, const float* __restrict__ E,
    float* __restrict__ C, __half* __restrict__ P,
    int N, int ktK, int mode)
{
    extern __shared__ char sm[];
    const uint32_t sb = smem_u32(sm);
    const int tid = threadIdx.x, wid = tid >> 5, lane = tid & 31;

    const uint32_t MFULL  = sb;
    const uint32_t MEMPTY = sb + 256;
    const uint32_t SA     = sb + 1024;
    const uint32_t SBq    = SA + G_STG * G_TB;

    if (tid == 0) {
        #pragma unroll
        for (int s = 0; s < G_STG; s++) { MBAR_INIT(MFULL + s*8, 1); MBAR_INIT(MEMPTY + s*8, 8); }
    }
    __syncthreads();

    const int gridN = gridDim.x;
    const int bid   = blockIdx.y * gridN + blockIdx.x;
    const int tpg   = GROUP_M * gridN;
    const int grp   = bid / tpg, rem = bid - grp * tpg;
    const int mt    = grp * GROUP_M + (rem % GROUP_M);
    const int nt    = rem / GROUP_M;

    float d[2][8][4];
    #pragma unroll
    for (int a = 0; a < 2; a++)
        #pragma unroll
        for (int b = 0; b < 8; b++)
            #pragma unroll
            for (int c = 0; c < 4; c++) d[a][b][c] = 0.f;

    if (wid == 8) {
        if (elect_one()) {
            const char* Ag = (const char*)A2 + (size_t)mt * ktK * G_TB;
            const char* Bg = (const char*)B2 + (size_t)nt * ktK * G_TB;
            int s = 0, ph = 1;
            for (int kt = 0; kt < ktK; kt++) {
                MBAR_WAIT(MEMPTY + s*8, ph);
                MBAR_EXPECT(MFULL + s*8, 2*G_TB);
                BULK_G2S(SA  + s*G_TB, Ag + (size_t)kt*G_TB, G_TB, MFULL + s*8);
                BULK_G2S(SBq + s*G_TB, Bg + (size_t)kt*G_TB, G_TB, MFULL + s*8);
                if (++s == G_STG) { s = 0; ph ^= 1; }
            }
        }
    } else {
        const int wm = (wid & 3) * 32;
        const int wn = (wid >> 2) * 64;
        const uint32_t rsub   = (uint32_t)(((lane >> 3) & 1) * 8 + (lane & 7));
        const uint32_t ksel   = (uint32_t)((lane >> 4) * 16);
        const uint32_t cmask  = (uint32_t)((lane & 7) << 4);
        const uint32_t aRowOff = (uint32_t)(wm + rsub) * 128;
        const uint32_t bRowOff = (uint32_t)(wn + rsub) * 128;

        int s = 0, ph = 0;
        for (int kt = 0; kt < ktK; kt++) {
            MBAR_WAIT(MFULL + s*8, ph);
            const uint32_t sa  = SA  + s*G_TB;
            const uint32_t sbb = SBq + s*G_TB;
            #pragma unroll
            for (int kk4 = 0; kk4 < 4; kk4++) {
                const uint32_t ko = (uint32_t)(kk4*32 + ksel) ^ cmask;
                uint32_t af[2][4];
                #pragma unroll
                for (int mi = 0; mi < 2; mi++)
                    LDSM_X4(af[mi][0], af[mi][1], af[mi][2], af[mi][3],
                            sa + aRowOff + mi*2048 + ko);
                uint32_t bf[8][2];
                #pragma unroll
                for (int ng = 0; ng < 4; ng++) {
                    uint32_t t0, t1, t2, t3;
                    LDSM_X4(t0, t1, t2, t3, sbb + bRowOff + ng*2048 + ko);
                    bf[2*ng][0] = t0; bf[2*ng+1][0] = t1;
                    bf[2*ng][1] = t2; bf[2*ng+1][1] = t3;
                }
                #pragma unroll
                for (int mi = 0; mi < 2; mi++)
                    #pragma unroll
                    for (int ni = 0; ni < 8; ni++)
                        MMA16816H(d[mi][ni], af[mi], bf[ni]);
            }
            if (lane == 0) MBAR_ARRIVE(MEMPTY + s*8);
            if (++s == G_STG) { s = 0; ph ^= 1; }
        }
    }

    __syncthreads();

    float* st = (float*)(sm + 1024);
    if (wid < 8) {
        const int wm = (wid & 3) * 32;
        const int wn = (wid >> 2) * 64;
        const int r0 = lane >> 2;
        const int cc = (lane & 3) * 2;
        #pragma unroll
        for (int mi = 0; mi < 2; mi++)
            #pragma unroll
            for (int ni = 0; ni < 8; ni++) {
                const int r = wm + mi*16 + r0;
                const int c = wn + ni*8 + cc;
                st[r*132 + c]       = d[mi][ni][0];
                st[r*132 + c + 1]   = d[mi][ni][1];
                st[(r+8)*132 + c]   = d[mi][ni][2];
                st[(r+8)*132 + c+1] = d[mi][ni][3];
            }
    }
    __syncthreads();

    if (tid < 256) {
        const int r0 = tid >> 5;
        const int c  = (tid & 31) * 4;
        const int n  = nt*128 + c;
        float4 bv = make_float4(0.f, 0.f, 0.f, 0.f);
        if (bias) bv = *(const float4*)(bias + n);
        #pragma unroll 4
        for (int rp = 0; rp < 16; rp++) {
            const int r = rp*8 + r0;
            const size_t idx = (size_t)(mt*128 + r) * N + n;
            float4 v = *(float4*)&st[r*132 + c];
            v.x += bv.x; v.y += bv.y; v.z += bv.z; v.w += bv.w;
            if (mode == 1) {
                float4 e = *(const float4*)(E + idx);
                v.x = e.x + fmaxf(v.x, 0.f); v.y = e.y + fmaxf(v.y, 0.f);
                v.z = e.z + fmaxf(v.z, 0.f); v.w = e.w + fmaxf(v.w, 0.f);
            } else if (mode == 2) {
                float4 e = *(const float4*)(E + idx);
                v.x += e.x; v.y += e.y; v.z += e.z; v.w += e.w;
            }
            if (P) pack4H((char*)P, N >> 6, mt*128 + r, n, v);
            else   *(float4*)(C + idx) = v;
        }
    }
}

// ---------------- tf32 tensor-core causal flash attention -> packed -----------
#define AT_SMEMF (3*64*132 + 64*68 + 128)
__global__ __launch_bounds__(256) void attn_tc(
    const float* __restrict__ qkv, __half* __restrict__ outP)
{
    extern __shared__ float s[];
    float* Qs = s;
    float* Ks = Qs + 64*132;
    float* Vs = Ks + 64*132;
    float* Sb = Vs + 64*132;
    float* Cr = Sb + 64*68;
    float* Ll = Cr + 64;

    const int tid = threadIdx.x, wid = tid >> 5, lane = tid & 31;
    const int qt = blockIdx.x, hh = blockIdx.y, bb = blockIdx.z;
    const int q0 = qt * 64;

    #pragma unroll
    for (int i = 0; i < 8; i++) {
        int id = i*256 + tid;
        int rr = id >> 5, c4 = (id & 31) * 4;
        float4 v = *(const float4*)(qkv + (size_t)(bb*SS + q0 + rr) * QKVW + hh*HD + c4);
        Qs[rr*132 + c4 + 0] = to_tf32(v.x * 0.08838834764831845f);
        Qs[rr*132 + c4 + 1] = to_tf32(v.y * 0.08838834764831845f);
        Qs[rr*132 + c4 + 2] = to_tf32(v.z * 0.08838834764831845f);
        Qs[rr*132 + c4 + 3] = to_tf32(v.w * 0.08838834764831845f);
    }

    const int srow = tid >> 2;
    const int sg   = tid & 3;
    float mrun = -INFINITY, lrun = 0.f;

    float o[8][4];
    #pragma unroll
    for (int i = 0; i < 8; i++)
        #pragma unroll
        for (int j = 0; j < 4; j++) o[i][j] = 0.f;

    const int wm  = (wid & 3) * 16;
    const int wnk = (wid >> 2) * 32;
    const int wnv = (wid >> 2) * 64;
    const int rA0 = wm + lane/4, rA1 = rA0 + 8;

    const int njt = qt + 1;
    for (int jt = 0; jt < njt; jt++) {
        const int j0 = jt * 64;
        __syncthreads();
        #pragma unroll
        for (int i = 0; i < 8; i++) {
            int id = i*256 + tid;
            int rr = id >> 5, c4 = (id & 31) * 4;
            size_t base = (size_t)(bb*SS + j0 + rr) * QKVW + hh*HD + c4;
            float4 kv = *(const float4*)(qkv + base + HH*HD);
            float4 vv = *(const float4*)(qkv + base + 2*HH*HD);
            Ks[rr*132 + c4 + 0] = to_tf32(kv.x); Ks[rr*132 + c4 + 1] = to_tf32(kv.y);
            Ks[rr*132 + c4 + 2] = to_tf32(kv.z); Ks[rr*132 + c4 + 3] = to_tf32(kv.w);
            Vs[rr*132 + c4 + 0] = to_tf32(vv.x); Vs[rr*132 + c4 + 1] = to_tf32(vv.y);
            Vs[rr*132 + c4 + 2] = to_tf32(vv.z); Vs[rr*132 + c4 + 3] = to_tf32(vv.w);
        }
        __syncthreads();

        {
            float c[4][4];
            #pragma unroll
            for (int i = 0; i < 4; i++)
                #pragma unroll
                for (int j = 0; j < 4; j++) c[i][j] = 0.f;
            #pragma unroll
            for (int ks = 0; ks < 16; ks++) {
                const int k0 = ks*8 + (lane & 3);
                uint32_t a0 = __float_as_uint(Qs[rA0*132 + k0]);
                uint32_t a1 = __float_as_uint(Qs[rA1*132 + k0]);
                uint32_t a2 = __float_as_uint(Qs[rA0*132 + k0 + 4]);
                uint32_t a3 = __float_as_uint(Qs[rA1*132 + k0 + 4]);
                #pragma unroll
                for (int ntl = 0; ntl < 4; ntl++) {
                    const int nrow = wnk + ntl*8 + lane/4;
                    uint32_t b0 = __float_as_uint(Ks[nrow*132 + k0]);
                    uint32_t b1 = __float_as_uint(Ks[nrow*132 + k0 + 4]);
                    MMA1688TF(c[ntl], a0, a1, a2, a3, b0, b1);
                }
            }
            const int cc = (lane & 3) * 2;
            #pragma unroll
            for (int ntl = 0; ntl < 4; ntl++) {
                const int cb = wnk + ntl*8 + cc;
                Sb[rA0*68 + cb]     = c[ntl][0];
                Sb[rA0*68 + cb + 1] = c[ntl][1];
                Sb[rA1*68 + cb]     = c[ntl][2];
                Sb[rA1*68 + cb + 1] = c[ntl][3];
            }
        }
        __syncthreads();

        {
            const bool diag = (jt == qt);
            const int qi_rel = srow;
            float mx = -INFINITY;
            float pv[16];
            #pragma unroll
            for (int j = 0; j < 16; j++) {
                const int c = sg + 4*j;
                float v = Sb[srow*68 + c];
                if (diag && c > qi_rel) v = -INFINITY;
                pv[j] = v;
                mx = fmaxf(mx, v);
            }
            mx = fmaxf(mx, __shfl_xor_sync(0xffffffffu, mx, 1));
            mx = fmaxf(mx, __shfl_xor_sync(0xffffffffu, mx, 2));
            const float mNew = fmaxf(mrun, mx);
            const float corr = __expf(mrun - mNew);
            float ls = 0.f;
            #pragma unroll
            for (int j = 0; j < 16; j++) {
                const int c = sg + 4*j;
                float p = (pv[j] == -INFINITY) ? 0.f : to_tf32(__expf(pv[j] - mNew));
                Sb[srow*68 + c] = p;
                ls += p;
            }
            ls += __shfl_xor_sync(0xffffffffu, ls, 1);
            ls += __shfl_xor_sync(0xffffffffu, ls, 2);
            lrun = lrun * corr + ls;
            mrun = mNew;
            if (sg == 0) { Cr[srow] = corr; Ll[srow] = lrun; }
        }
        __syncthreads();

        {
            const float c0 = Cr[rA0], c1 = Cr[rA1];
            #pragma unroll
            for (int i = 0; i < 8; i++) {
                o[i][0] *= c0; o[i][1] *= c0;
                o[i][2] *= c1; o[i][3] *= c1;
            }
            #pragma unroll
            for (int ks = 0; ks < 8; ks++) {
                const int k0 = ks*8 + (lane & 3);
                uint32_t a0 = __float_as_uint(Sb[rA0*68 + k0]);
                uint32_t a1 = __float_as_uint(Sb[rA1*68 + k0]);
                uint32_t a2 = __float_as_uint(Sb[rA0*68 + k0 + 4]);
                uint32_t a3 = __float_as_uint(Sb[rA1*68 + k0 + 4]);
                #pragma unroll
                for (int ntl = 0; ntl < 8; ntl++) {
                    const int ncol = wnv + ntl*8 + lane/4;
                    uint32_t b0 = __float_as_uint(Vs[k0*132 + ncol]);
                    uint32_t b1 = __float_as_uint(Vs[(k0+4)*132 + ncol]);
                    MMA1688TF(o[ntl], a0, a1, a2, a3, b0, b1);
                }
            }
        }
    }
    __syncthreads();

    {
        const float inv0 = 1.f / Ll[rA0];
        const float inv1 = 1.f / Ll[rA1];
        const int t0 = (bb*HH + hh)*SS + q0 + rA0;
        const int t1 = (bb*HH + hh)*SS + q0 + rA1;
        const int m0 = t0 >> 4, cB0 = (t0 & 15) * 128;
        const int m1 = t1 >> 4, cB1 = (t1 & 15) * 128;
        const int cc = (lane & 3) * 2;
        #pragma unroll
        for (int ntl = 0; ntl < 8; ntl++) {
            const int cb = wnv + ntl*8 + cc;
            pack2H((char*)outP, DD/64, m0, cB0 + cb, o[ntl][0]*inv0, o[ntl][1]*inv0);
            pack2H((char*)outP, DD/64, m1, cB1 + cb, o[ntl][2]*inv1, o[ntl][3]*inv1);
        }
    }
}

// ---------------- launch --------------------------------------------------------
extern "C" void kernel_launch(void* const* d_in, const int* in_sizes, int n_in,
                              void* d_out, int out_size)
{
    (void)in_sizes; (void)n_in; (void)out_size;
    const float* x     = (const float*)d_in[0];
    const float* rms_w = (const float*)d_in[1];
    const float* w_qkv = (const float*)d_in[2];
    const float* w_out = (const float*)d_in[3];
    const float* w1    = (const float*)d_in[4];
    const float* b1    = (const float*)d_in[5];
    const float* w3    = (const float*)d_in[6];
    const float* b3    = (const float*)d_in[7];
    const float* w2    = (const float*)d_in[8];
    const float* b2    = (const float*)d_in[9];
    float* out = (float*)d_out;

    float *qkv, *a1;
    cudaGetSymbolAddress((void**)&qkv, g_qkv);
    cudaGetSymbolAddress((void**)&a1,  g_a1);
    __half *xn2,*att2,*h2,*gg2,*wqkv2,*wout2,*w12,*w32,*w22;
    cudaGetSymbolAddress((void**)&xn2,   g_xn2);
    cudaGetSymbolAddress((void**)&att2,  g_att2);
    cudaGetSymbolAddress((void**)&h2,    g_h2);
    cudaGetSymbolAddress((void**)&gg2,   g_gg2);
    cudaGetSymbolAddress((void**)&wqkv2, g_wqkv2);
    cudaGetSymbolAddress((void**)&wout2, g_wout2);
    cudaGetSymbolAddress((void**)&w12,   g_w12);
    cudaGetSymbolAddress((void**)&w32,   g_w32);
    cudaGetSymbolAddress((void**)&w22,   g_w22);

    cudaFuncSetAttribute(gemm_mma, cudaFuncAttributeMaxDynamicSharedMemorySize, G_SMEM);
    const int attn_smem = AT_SMEMF * (int)sizeof(float);
    cudaFuncSetAttribute(attn_tc, cudaFuncAttributeMaxDynamicSharedMemorySize, attn_smem);

    // weight conversions (hi-only)
    convW<<<(QKVW*DD/4 + 255)/256, 256>>>(w_qkv, wqkv2, DD, QKVW*DD/4);
    convW<<<(DD*DD/4   + 255)/256, 256>>>(w_out, wout2, DD, DD*DD/4);
    convW<<<(FF*DD/4   + 255)/256, 256>>>(w1,    w12,   DD, FF*DD/4);
    convW<<<(FF*DD/4   + 255)/256, 256>>>(w3,    w32,   DD, FF*DD/4);
    convW<<<(DD*FF/4   + 255)/256, 256>>>(w2,    w22,   FF, DD*FF/4);

    // 1) RMSNorm -> packed
    rmsnorm_pack<<<MM, 256>>>(x, rms_w, xn2);

    // 2) QKV projection (fp32 out for attention)
    gemm_mma<<<dim3(QKVW/128, MM/128), 288, G_SMEM>>>(
        xn2, wqkv2, nullptr, nullptr, qkv, nullptr, QKVW, DD/64, 0);

    // 3) attention -> packed att2
    attn_tc<<<dim3(SS/64, HH, BB), 256, attn_smem>>>(qkv, att2);

    // 4) out projection -> packed h2
    gemm_mma<<<dim3(DD/128, MM/128), 288, G_SMEM>>>(
        att2, wout2, nullptr, nullptr, nullptr, h2, DD, DD/64, 0);

    // 5) a1 = h @ w1^T + b1 (fp32, consumed as E)
    gemm_mma<<<dim3(FF/128, MM/128), 288, G_SMEM>>>(
        h2, w12, b1, nullptr, a1, nullptr, FF, DD/64, 0);

    // 6) gg = a1 + relu(h @ w3^T + b3) -> packed gg2
    gemm_mma<<<dim3(FF/128, MM/128), 288, G_SMEM>>>(
        h2, w32, b3, a1, nullptr, gg2, FF, DD/64, 1);

    // 7) out = x + gg @ w2^T + b2 (fp32 final)
    gemm_mma<<<dim3(DD/128, MM/128), 288, G_SMEM>>>(
        gg2, w22, b2, x, out, nullptr, DD, FF/64, 2);
}

// round 10
// speedup vs baseline: 2.1240x; 1.2122x over previous
#include <cuda_runtime.h>
#include <cuda_fp16.h>
#include <math.h>
#include <stdint.h>

#define BB   2
#define SS   2048
#define DD   2048
#define HH   16
#define HD   128
#define FF   8192
#define MM   (BB*SS)          // 4096
#define QKVW (3*DD)           // 6144

// ---------------- scratch ----------------
__device__ float  g_a1  [MM*FF];
__device__ __half g_qkvh[(size_t)MM*QKVW];     // fp16 row-major qkv
// fp16 packed (tiled [rows/128][K/64][128][64], SW128)
__device__ __half g_xn2 [(size_t)MM*DD];
__device__ __half g_att2[(size_t)MM*DD];
__device__ __half g_h2  [(size_t)MM*DD];
__device__ __half g_gg2 [(size_t)MM*FF];
__device__ __half g_wqkv2[(size_t)QKVW*DD];
__device__ __half g_wout2[(size_t)DD*DD];
__device__ __half g_w12 [(size_t)FF*DD];
__device__ __half g_w32 [(size_t)FF*DD];
__device__ __half g_w22 [(size_t)DD*FF];

// ---------------- PTX helpers -------------------------------------------------
__device__ __forceinline__ uint32_t smem_u32(const void* p) {
    uint32_t a;
    asm("{ .reg .u64 t; cvta.to.shared.u64 t, %1; cvt.u32.u64 %0, t; }" : "=r"(a) : "l"(p));
    return a;
}
__device__ __forceinline__ uint32_t elect_one() {
    uint32_t p;
    asm volatile("{ .reg .pred p; elect.sync _|p, 0xFFFFFFFF; selp.b32 %0,1,0,p; }" : "=r"(p));
    return p;
}
#define MBAR_INIT(a, c) \
    asm volatile("mbarrier.init.shared.b64 [%0], %1;" :: "r"(a), "r"(c) : "memory")
#define MBAR_EXPECT(a, b) \
    asm volatile("mbarrier.arrive.expect_tx.shared.b64 _, [%0], %1;" :: "r"(a), "r"(b) : "memory")
#define MBAR_ARRIVE(a) \
    asm volatile("mbarrier.arrive.shared.b64 _, [%0];" :: "r"(a) : "memory")
#define MBAR_WAIT(a, ph) do { uint32_t _m=(a), _p=(ph), _d;                                   \
    asm volatile("{ .reg .pred p; mbarrier.try_wait.parity.acquire.cta.shared::cta.b64 p, [%1], %2; selp.b32 %0,1,0,p; }" \
                 : "=r"(_d) : "r"(_m), "r"(_p) : "memory");                                   \
    if (!_d) {                                                                                \
      asm volatile("{ .reg .pred P1; WL%=: mbarrier.try_wait.parity.acquire.cta.shared::cta.b64 P1, [%0], %1, 0x989680; @P1 bra.uni WD%=; bra.uni WL%=; WD%=: }" \
                   :: "r"(_m), "r"(_p) : "memory"); } } while(0)
#define BULK_G2S(d, s, n, m) \
    asm volatile("cp.async.bulk.shared::cta.global.mbarrier::complete_tx::bytes [%0], [%1], %2, [%3];" \
                 :: "r"(d), "l"(s), "r"(n), "r"(m) : "memory")
#define LDSM_X4(r0, r1, r2, r3, a) \
    asm volatile("ldmatrix.sync.aligned.m8n8.x4.shared.b16 {%0,%1,%2,%3}, [%4];" \
                 : "=r"(r0), "=r"(r1), "=r"(r2), "=r"(r3) : "r"(a))
#define LDSM_X4T(r0, r1, r2, r3, a) \
    asm volatile("ldmatrix.sync.aligned.m8n8.x4.trans.shared.b16 {%0,%1,%2,%3}, [%4];" \
                 : "=r"(r0), "=r"(r1), "=r"(r2), "=r"(r3) : "r"(a))
#define MMA16816H(d, av, bv) \
    asm volatile("mma.sync.aligned.m16n8k16.row.col.f32.f16.f16.f32 " \
                 "{%0,%1,%2,%3}, {%4,%5,%6,%7}, {%8,%9}, {%0,%1,%2,%3};" \
                 : "+f"((d)[0]), "+f"((d)[1]), "+f"((d)[2]), "+f"((d)[3]) \
                 : "r"((av)[0]), "r"((av)[1]), "r"((av)[2]), "r"((av)[3]), \
                   "r"((bv)[0]), "r"((bv)[1]))

// ---------------- fp16 pack helpers --------------------------------------------
__device__ __forceinline__ uint32_t h2pack(float v0, float v1) {
    return (uint32_t)__half_as_ushort(__float2half_rn(v0))
         | ((uint32_t)__half_as_ushort(__float2half_rn(v1)) << 16);
}
__device__ __forceinline__ void pack4H(char* base, int ktK, int m, int n, float4 v) {
    const int mt = m >> 7, mr = m & 127;
    const int kt = n >> 6, c = n & 63;
    const size_t tb = ((size_t)mt * ktK + kt) * 16384;
    uint32_t off = (uint32_t)(mr * 128 + c * 2);
    off ^= (off >> 3) & 0x70;
    *(uint2*)(base + tb + off) = make_uint2(h2pack(v.x, v.y), h2pack(v.z, v.w));
}
__device__ __forceinline__ void pack2H(char* base, int ktK, int m, int n, float v0, float v1) {
    const int mt = m >> 7, mr = m & 127;
    const int kt = n >> 6, c = n & 63;
    const size_t tb = ((size_t)mt * ktK + kt) * 16384;
    uint32_t off = (uint32_t)(mr * 128 + c * 2);
    off ^= (off >> 3) & 0x70;
    *(uint32_t*)(base + tb + off) = h2pack(v0, v1);
}

// ---------------- RMSNorm -> packed fp16 ---------------------------------------
__global__ __launch_bounds__(256) void rmsnorm_pack(
    const float* __restrict__ x, const float* __restrict__ w, __half* __restrict__ dst)
{
    const int row = blockIdx.x;
    const float4* xr = (const float4*)(x + (size_t)row * DD);
    float4 a = xr[threadIdx.x];
    float4 b = xr[threadIdx.x + 256];
    float ss = a.x*a.x + a.y*a.y + a.z*a.z + a.w*a.w
             + b.x*b.x + b.y*b.y + b.z*b.z + b.w*b.w;
    #pragma unroll
    for (int o = 16; o; o >>= 1) ss += __shfl_xor_sync(0xffffffffu, ss, o);
    __shared__ float sred[8];
    if ((threadIdx.x & 31) == 0) sred[threadIdx.x >> 5] = ss;
    __syncthreads();
    float tot = sred[0]+sred[1]+sred[2]+sred[3]+sred[4]+sred[5]+sred[6]+sred[7];
    float sc = rsqrtf(tot * (1.0f / DD) + 1e-5f);

    const float4* wr = (const float4*)w;
    #pragma unroll
    for (int g = 0; g < 2; g++) {
        const int gi = threadIdx.x + g*256;
        float4 v = (g == 0) ? a : b;
        float4 wv = wr[gi];
        v.x *= sc * wv.x; v.y *= sc * wv.y; v.z *= sc * wv.z; v.w *= sc * wv.w;
        pack4H((char*)dst, DD/64, row, gi*4, v);
    }
}

// ---------------- weight fp32 -> fp16 tile-packed ------------------------------
__global__ __launch_bounds__(256) void convW(
    const float* __restrict__ src, __half* __restrict__ dst, int K, int total4)
{
    int gid = blockIdx.x * 256 + threadIdx.x;
    if (gid >= total4) return;
    const int kq = K >> 2;
    const int m  = gid / kq;
    const int k  = (gid - m * kq) << 2;
    float4 v = *(const float4*)(src + (size_t)m * K + k);
    pack4H((char*)dst, K >> 6, m, k, v);
}

// ---------------- fp16 mma.sync GEMM --------------------------------------------
// 128x128 tile, 8 math warps + producer; 3 stages; 2 CTAs/SM.
// out: P -> packed tiled fp16 ; Hrow -> plain row-major fp16 ; else fp32 C.
#define G_STG    3
#define G_TB     16384
#define G_SMEM   (1024 + G_STG*2*G_TB)        // 99328
#define GROUP_M  8

__global__ __launch_bounds__(288, 2) void gemm_mma(
    const __half* __restrict__ A2, const __half* __restrict__ B2,
    const float* __restrict__ bias, const float* __restrict__ E,
    float* __restrict__ C, __half* __restrict__ P, __half* __restrict__ Hrow,
    int N, int ktK, int mode)
{
    extern __shared__ char sm[];
    const uint32_t sb = smem_u32(sm);
    const int tid = threadIdx.x, wid = tid >> 5, lane = tid & 31;

    const uint32_t MFULL  = sb;
    const uint32_t MEMPTY = sb + 256;
    const uint32_t SA     = sb + 1024;
    const uint32_t SBq    = SA + G_STG * G_TB;

    if (tid == 0) {
        #pragma unroll
        for (int s = 0; s < G_STG; s++) { MBAR_INIT(MFULL + s*8, 1); MBAR_INIT(MEMPTY + s*8, 8); }
    }
    __syncthreads();

    const int gridN = gridDim.x;
    const int bid   = blockIdx.y * gridN + blockIdx.x;
    const int tpg   = GROUP_M * gridN;
    const int grp   = bid / tpg, rem = bid - grp * tpg;
    const int mt    = grp * GROUP_M + (rem % GROUP_M);
    const int nt    = rem / GROUP_M;

    float d[2][8][4];
    #pragma unroll
    for (int a = 0; a < 2; a++)
        #pragma unroll
        for (int b = 0; b < 8; b++)
            #pragma unroll
            for (int c = 0; c < 4; c++) d[a][b][c] = 0.f;

    if (wid == 8) {
        if (elect_one()) {
            const char* Ag = (const char*)A2 + (size_t)mt * ktK * G_TB;
            const char* Bg = (const char*)B2 + (size_t)nt * ktK * G_TB;
            int s = 0, ph = 1;
            for (int kt = 0; kt < ktK; kt++) {
                MBAR_WAIT(MEMPTY + s*8, ph);
                MBAR_EXPECT(MFULL + s*8, 2*G_TB);
                BULK_G2S(SA  + s*G_TB, Ag + (size_t)kt*G_TB, G_TB, MFULL + s*8);
                BULK_G2S(SBq + s*G_TB, Bg + (size_t)kt*G_TB, G_TB, MFULL + s*8);
                if (++s == G_STG) { s = 0; ph ^= 1; }
            }
        }
    } else {
        const int wm = (wid & 3) * 32;
        const int wn = (wid >> 2) * 64;
        const uint32_t rsub   = (uint32_t)(((lane >> 3) & 1) * 8 + (lane & 7));
        const uint32_t ksel   = (uint32_t)((lane >> 4) * 16);
        const uint32_t cmask  = (uint32_t)((lane & 7) << 4);
        const uint32_t aRowOff = (uint32_t)(wm + rsub) * 128;
        const uint32_t bRowOff = (uint32_t)(wn + rsub) * 128;

        int s = 0, ph = 0;
        for (int kt = 0; kt < ktK; kt++) {
            MBAR_WAIT(MFULL + s*8, ph);
            const uint32_t sa  = SA  + s*G_TB;
            const uint32_t sbb = SBq + s*G_TB;
            #pragma unroll
            for (int kk4 = 0; kk4 < 4; kk4++) {
                const uint32_t ko = (uint32_t)(kk4*32 + ksel) ^ cmask;
                uint32_t af[2][4];
                #pragma unroll
                for (int mi = 0; mi < 2; mi++)
                    LDSM_X4(af[mi][0], af[mi][1], af[mi][2], af[mi][3],
                            sa + aRowOff + mi*2048 + ko);
                uint32_t bf[8][2];
                #pragma unroll
                for (int ng = 0; ng < 4; ng++) {
                    uint32_t t0, t1, t2, t3;
                    LDSM_X4(t0, t1, t2, t3, sbb + bRowOff + ng*2048 + ko);
                    bf[2*ng][0] = t0; bf[2*ng+1][0] = t1;
                    bf[2*ng][1] = t2; bf[2*ng+1][1] = t3;
                }
                #pragma unroll
                for (int mi = 0; mi < 2; mi++)
                    #pragma unroll
                    for (int ni = 0; ni < 8; ni++)
                        MMA16816H(d[mi][ni], af[mi], bf[ni]);
            }
            if (lane == 0) MBAR_ARRIVE(MEMPTY + s*8);
            if (++s == G_STG) { s = 0; ph ^= 1; }
        }
    }

    __syncthreads();

    float* st = (float*)(sm + 1024);
    if (wid < 8) {
        const int wm = (wid & 3) * 32;
        const int wn = (wid >> 2) * 64;
        const int r0 = lane >> 2;
        const int cc = (lane & 3) * 2;
        #pragma unroll
        for (int mi = 0; mi < 2; mi++)
            #pragma unroll
            for (int ni = 0; ni < 8; ni++) {
                const int r = wm + mi*16 + r0;
                const int c = wn + ni*8 + cc;
                st[r*132 + c]       = d[mi][ni][0];
                st[r*132 + c + 1]   = d[mi][ni][1];
                st[(r+8)*132 + c]   = d[mi][ni][2];
                st[(r+8)*132 + c+1] = d[mi][ni][3];
            }
    }
    __syncthreads();

    if (tid < 256) {
        const int r0 = tid >> 5;
        const int c  = (tid & 31) * 4;
        const int n  = nt*128 + c;
        float4 bv = make_float4(0.f, 0.f, 0.f, 0.f);
        if (bias) bv = *(const float4*)(bias + n);
        #pragma unroll 4
        for (int rp = 0; rp < 16; rp++) {
            const int r = rp*8 + r0;
            const size_t idx = (size_t)(mt*128 + r) * N + n;
            float4 v = *(float4*)&st[r*132 + c];
            v.x += bv.x; v.y += bv.y; v.z += bv.z; v.w += bv.w;
            if (mode == 1) {
                float4 e = *(const float4*)(E + idx);
                v.x = e.x + fmaxf(v.x, 0.f); v.y = e.y + fmaxf(v.y, 0.f);
                v.z = e.z + fmaxf(v.z, 0.f); v.w = e.w + fmaxf(v.w, 0.f);
            } else if (mode == 2) {
                float4 e = *(const float4*)(E + idx);
                v.x += e.x; v.y += e.y; v.z += e.z; v.w += e.w;
            }
            if (P)         pack4H((char*)P, N >> 6, mt*128 + r, n, v);
            else if (Hrow) *(uint2*)(Hrow + idx) = make_uint2(h2pack(v.x, v.y), h2pack(v.z, v.w));
            else           *(float4*)(C + idx) = v;
        }
    }
}

// ---------------- fp16 tensor-core causal flash attention -> packed -------------
// smem: Q/K/V 2x[64][64] swizzled fp16 tiles each + P [64][64] + fp32 softmax state
#define AT_SMEM (3*16384 + 8192 + 64*68*4 + 512 + 1024)   // ~76KB
#define ASCALE  0.08838834764831845f

__global__ __launch_bounds__(256, 2) void attn_fp16(
    const __half* __restrict__ qkvh, __half* __restrict__ outP)
{
    extern __shared__ char smc[];
    const uint32_t qb = smem_u32(smc);
    const uint32_t kb = qb + 16384;
    const uint32_t vb = kb + 16384;
    const uint32_t pb = vb + 16384;
    float* Sb = (float*)(smc + 3*16384 + 8192);
    float* Cr = Sb + 64*68;
    float* Ll = Cr + 64;

    const int tid = threadIdx.x, wid = tid >> 5, lane = tid & 31;
    const int qt = blockIdx.x, hh = blockIdx.y, bb = blockIdx.z;
    const int q0 = qt * 64;

    // ---- load Q tiles (rows 64 x 128 halfs -> 2 swizzled [64][64] tiles)
    #pragma unroll
    for (int i = 0; i < 4; i++) {
        const int id = i*256 + tid;
        const int rr = id >> 4, oc = id & 15;
        uint4 v = *(const uint4*)(qkvh + (size_t)(bb*SS + q0 + rr) * QKVW + hh*HD + oc*8);
        uint32_t off = (uint32_t)(rr*128 + (oc & 7)*16);
        off ^= (off >> 3) & 0x70;
        *(uint4*)(smc + (size_t)(oc >> 3)*8192 + off) = v;
    }

    const int srow = tid >> 2;
    const int sg   = tid & 3;
    float mrun = -INFINITY, lrun = 0.f;

    float o[8][4];
    #pragma unroll
    for (int i = 0; i < 8; i++)
        #pragma unroll
        for (int j = 0; j < 4; j++) o[i][j] = 0.f;

    const int wm  = (wid & 3) * 16;
    const int wnk = (wid >> 2) * 32;
    const int wnv = (wid >> 2) * 64;
    const int rA0 = wm + lane/4, rA1 = rA0 + 8;
    const uint32_t rsub  = (uint32_t)(((lane >> 3) & 1) * 8 + (lane & 7));
    const uint32_t ksel  = (uint32_t)((lane >> 4) * 16);
    const uint32_t cmask = (uint32_t)((lane & 7) << 4);
    const uint32_t aRowOff = (uint32_t)(wm + rsub) * 128;
    // trans-ldmatrix (V) lane addressing
    const int vrow = lane & 15;
    const int voct = lane >> 4;

    const int njt = qt + 1;
    for (int jt = 0; jt < njt; jt++) {
        const int j0 = jt * 64;
        __syncthreads();
        // ---- load K, V tiles
        #pragma unroll
        for (int i = 0; i < 4; i++) {
            const int id = i*256 + tid;
            const int rr = id >> 4, oc = id & 15;
            const __half* base = qkvh + (size_t)(bb*SS + j0 + rr) * QKVW + hh*HD + oc*8;
            uint4 kvv = *(const uint4*)(base + 16*HD);      // K block
            uint4 vvv = *(const uint4*)(base + 32*HD);      // V block
            uint32_t off = (uint32_t)(rr*128 + (oc & 7)*16);
            off ^= (off >> 3) & 0x70;
            const size_t toff = (size_t)(oc >> 3)*8192 + off;
            *(uint4*)(smc + 16384 + toff) = kvv;
            *(uint4*)(smc + 32768 + toff) = vvv;
        }
        __syncthreads();

        // ---- QK^T (fp16 mma): scores 64x64
        {
            float c[4][4];
            #pragma unroll
            for (int i = 0; i < 4; i++)
                #pragma unroll
                for (int j = 0; j < 4; j++) c[i][j] = 0.f;
            #pragma unroll
            for (int t = 0; t < 2; t++) {
                #pragma unroll
                for (int kk4 = 0; kk4 < 4; kk4++) {
                    const uint32_t ko = (uint32_t)(kk4*32 + ksel) ^ cmask;
                    uint32_t af[4];
                    LDSM_X4(af[0], af[1], af[2], af[3], qb + t*8192 + aRowOff + ko);
                    uint32_t bf[4][2];
                    #pragma unroll
                    for (int ng = 0; ng < 2; ng++) {
                        uint32_t t0, t1, t2, t3;
                        LDSM_X4(t0, t1, t2, t3,
                                kb + t*8192 + (uint32_t)(wnk + ng*16 + rsub)*128 + ko);
                        bf[2*ng][0] = t0; bf[2*ng+1][0] = t1;
                        bf[2*ng][1] = t2; bf[2*ng+1][1] = t3;
                    }
                    #pragma unroll
                    for (int ntl = 0; ntl < 4; ntl++)
                        MMA16816H(c[ntl], af, bf[ntl]);
                }
            }
            const int cc = (lane & 3) * 2;
            #pragma unroll
            for (int ntl = 0; ntl < 4; ntl++) {
                const int cb = wnk + ntl*8 + cc;
                Sb[rA0*68 + cb]     = c[ntl][0];
                Sb[rA0*68 + cb + 1] = c[ntl][1];
                Sb[rA1*68 + cb]     = c[ntl][2];
                Sb[rA1*68 + cb + 1] = c[ntl][3];
            }
        }
        __syncthreads();

        // ---- softmax (contiguous 16-col slice per lane) + write P fp16
        {
            const bool diag = (jt == qt);
            float pv[16];
            float mx = -INFINITY;
            #pragma unroll
            for (int t = 0; t < 16; t++) {
                const int cidx = sg*16 + t;
                float v = Sb[srow*68 + cidx] * ASCALE;
                if (diag && cidx > srow) v = -INFINITY;
                pv[t] = v;
                mx = fmaxf(mx, v);
            }
            mx = fmaxf(mx, __shfl_xor_sync(0xffffffffu, mx, 1));
            mx = fmaxf(mx, __shfl_xor_sync(0xffffffffu, mx, 2));
            const float mNew = fmaxf(mrun, mx);
            const float corr = __expf(mrun - mNew);
            float ls = 0.f;
            #pragma unroll
            for (int t2 = 0; t2 < 8; t2++) {
                float p0 = (pv[2*t2]   == -INFINITY) ? 0.f : __expf(pv[2*t2]   - mNew);
                float p1 = (pv[2*t2+1] == -INFINITY) ? 0.f : __expf(pv[2*t2+1] - mNew);
                ls += p0 + p1;
                uint32_t off = (uint32_t)(srow*128 + (sg*16 + 2*t2)*2);
                off ^= (off >> 3) & 0x70;
                *(uint32_t*)(smc + 3*16384 + off) = h2pack(p0, p1);
            }
            ls += __shfl_xor_sync(0xffffffffu, ls, 1);
            ls += __shfl_xor_sync(0xffffffffu, ls, 2);
            lrun = lrun * corr + ls;
            mrun = mNew;
            if (sg == 0) { Cr[srow] = corr; Ll[srow] = lrun; }
        }
        __syncthreads();

        // ---- PV (fp16 mma, V via ldmatrix.trans)
        {
            const float c0 = Cr[rA0], c1 = Cr[rA1];
            #pragma unroll
            for (int i = 0; i < 8; i++) {
                o[i][0] *= c0; o[i][1] *= c0;
                o[i][2] *= c1; o[i][3] *= c1;
            }
            const uint32_t vtile = vb + (uint32_t)(wnv >> 6) * 8192;
            #pragma unroll
            for (int kk4 = 0; kk4 < 4; kk4++) {
                const uint32_t ko = (uint32_t)(kk4*32 + ksel) ^ cmask;
                uint32_t af[4];
                LDSM_X4(af[0], af[1], af[2], af[3], pb + aRowOff + ko);
                const int row = kk4*16 + vrow;
                const uint32_t rkey = (uint32_t)((row & 7) << 4);
                #pragma unroll
                for (int pair = 0; pair < 4; pair++) {
                    const uint32_t bcol = (uint32_t)(pair*32 + voct*16) ^ rkey;
                    uint32_t t0, t1, t2, t3;
                    LDSM_X4T(t0, t1, t2, t3, vtile + (uint32_t)row*128 + bcol);
                    uint32_t b0[2] = {t0, t1};
                    uint32_t b1[2] = {t2, t3};
                    MMA16816H(o[pair*2],     af, b0);
                    MMA16816H(o[pair*2 + 1], af, b1);
                }
            }
        }
    }
    __syncthreads();

    // ---- normalize + packed store (raw-reshape [B*S, D] mapping)
    {
        const float inv0 = 1.f / Ll[rA0];
        const float inv1 = 1.f / Ll[rA1];
        const int t0i = (bb*HH + hh)*SS + q0 + rA0;
        const int t1i = (bb*HH + hh)*SS + q0 + rA1;
        const int m0 = t0i >> 4, cB0 = (t0i & 15) * 128;
        const int m1 = t1i >> 4, cB1 = (t1i & 15) * 128;
        const int cc = (lane & 3) * 2;
        #pragma unroll
        for (int ntl = 0; ntl < 8; ntl++) {
            const int cb = wnv + ntl*8 + cc;
            pack2H((char*)outP, DD/64, m0, cB0 + cb, o[ntl][0]*inv0, o[ntl][1]*inv0);
            pack2H((char*)outP, DD/64, m1, cB1 + cb, o[ntl][2]*inv1, o[ntl][3]*inv1);
        }
    }
}

// ---------------- launch --------------------------------------------------------
extern "C" void kernel_launch(void* const* d_in, const int* in_sizes, int n_in,
                              void* d_out, int out_size)
{
    (void)in_sizes; (void)n_in; (void)out_size;
    const float* x     = (const float*)d_in[0];
    const float* rms_w = (const float*)d_in[1];
    const float* w_qkv = (const float*)d_in[2];
    const float* w_out = (const float*)d_in[3];
    const float* w1    = (const float*)d_in[4];
    const float* b1    = (const float*)d_in[5];
    const float* w3    = (const float*)d_in[6];
    const float* b3    = (const float*)d_in[7];
    const float* w2    = (const float*)d_in[8];
    const float* b2    = (const float*)d_in[9];
    float* out = (float*)d_out;

    float* a1;
    cudaGetSymbolAddress((void**)&a1, g_a1);
    __half *qkvh,*xn2,*att2,*h2,*gg2,*wqkv2,*wout2,*w12,*w32,*w22;
    cudaGetSymbolAddress((void**)&qkvh,  g_qkvh);
    cudaGetSymbolAddress((void**)&xn2,   g_xn2);
    cudaGetSymbolAddress((void**)&att2,  g_att2);
    cudaGetSymbolAddress((void**)&h2,    g_h2);
    cudaGetSymbolAddress((void**)&gg2,   g_gg2);
    cudaGetSymbolAddress((void**)&wqkv2, g_wqkv2);
    cudaGetSymbolAddress((void**)&wout2, g_wout2);
    cudaGetSymbolAddress((void**)&w12,   g_w12);
    cudaGetSymbolAddress((void**)&w32,   g_w32);
    cudaGetSymbolAddress((void**)&w22,   g_w22);

    cudaFuncSetAttribute(gemm_mma, cudaFuncAttributeMaxDynamicSharedMemorySize, G_SMEM);
    cudaFuncSetAttribute(attn_fp16, cudaFuncAttributeMaxDynamicSharedMemorySize, AT_SMEM);

    // weight conversions
    convW<<<(QKVW*DD/4 + 255)/256, 256>>>(w_qkv, wqkv2, DD, QKVW*DD/4);
    convW<<<(DD*DD/4   + 255)/256, 256>>>(w_out, wout2, DD, DD*DD/4);
    convW<<<(FF*DD/4   + 255)/256, 256>>>(w1,    w12,   DD, FF*DD/4);
    convW<<<(FF*DD/4   + 255)/256, 256>>>(w3,    w32,   DD, FF*DD/4);
    convW<<<(DD*FF/4   + 255)/256, 256>>>(w2,    w22,   FF, DD*FF/4);

    // 1) RMSNorm -> packed
    rmsnorm_pack<<<MM, 256>>>(x, rms_w, xn2);

    // 2) QKV projection -> fp16 row-major
    gemm_mma<<<dim3(QKVW/128, MM/128), 288, G_SMEM>>>(
        xn2, wqkv2, nullptr, nullptr, nullptr, nullptr, qkvh, QKVW, DD/64, 0);

    // 3) attention (fp16 tensor cores) -> packed att2
    attn_fp16<<<dim3(SS/64, HH, BB), 256, AT_SMEM>>>(qkvh, att2);

    // 4) out projection -> packed h2
    gemm_mma<<<dim3(DD/128, MM/128), 288, G_SMEM>>>(
        att2, wout2, nullptr, nullptr, nullptr, h2, nullptr, DD, DD/64, 0);

    // 5) a1 = h @ w1^T + b1 (fp32, consumed as E)
    gemm_mma<<<dim3(FF/128, MM/128), 288, G_SMEM>>>(
        h2, w12, b1, nullptr, a1, nullptr, nullptr, FF, DD/64, 0);

    // 6) gg = a1 + relu(h @ w3^T + b3) -> packed gg2
    gemm_mma<<<dim3(FF/128, MM/128), 288, G_SMEM>>>(
        h2, w32, b3, a1, nullptr, gg2, nullptr, FF, DD/64, 1);

    // 7) out = x + gg @ w2^T + b2 (fp32 final)
    gemm_mma<<<dim3(DD/128, MM/128), 288, G_SMEM>>>(
        gg2, w22, b2, x, out, nullptr, nullptr, DD, FF/64, 2);
}

// round 11
// speedup vs baseline: 2.2206x; 1.0454x over previous
#include <cuda_runtime.h>
#include <cuda_fp16.h>
#include <math.h>
#include <stdint.h>

#define BB   2
#define SS   2048
#define DD   2048
#define HH   16
#define HD   128
#define FF   8192
#define MM   (BB*SS)          // 4096
#define QKVW (3*DD)           // 6144

// ---------------- scratch ----------------
__device__ __half g_qkvh[(size_t)MM*QKVW];     // fp16 row-major qkv
// fp16 packed (tiled [rows/128][K/64][128][64], SW128)
__device__ __half g_xn2 [(size_t)MM*DD];
__device__ __half g_att2[(size_t)MM*DD];
__device__ __half g_h2  [(size_t)MM*DD];
__device__ __half g_gg2 [(size_t)MM*FF];
__device__ __half g_wqkv2[(size_t)QKVW*DD];
__device__ __half g_wout2[(size_t)DD*DD];
__device__ __half g_w132[(size_t)2*FF*DD];     // w1/w3 row-interleaved
__device__ __half g_w22 [(size_t)DD*FF];

// ---------------- PTX helpers -------------------------------------------------
__device__ __forceinline__ uint32_t smem_u32(const void* p) {
    uint32_t a;
    asm("{ .reg .u64 t; cvta.to.shared.u64 t, %1; cvt.u32.u64 %0, t; }" : "=r"(a) : "l"(p));
    return a;
}
__device__ __forceinline__ uint32_t elect_one() {
    uint32_t p;
    asm volatile("{ .reg .pred p; elect.sync _|p, 0xFFFFFFFF; selp.b32 %0,1,0,p; }" : "=r"(p));
    return p;
}
#define MBAR_INIT(a, c) \
    asm volatile("mbarrier.init.shared.b64 [%0], %1;" :: "r"(a), "r"(c) : "memory")
#define MBAR_EXPECT(a, b) \
    asm volatile("mbarrier.arrive.expect_tx.shared.b64 _, [%0], %1;" :: "r"(a), "r"(b) : "memory")
#define MBAR_ARRIVE(a) \
    asm volatile("mbarrier.arrive.shared.b64 _, [%0];" :: "r"(a) : "memory")
#define MBAR_WAIT(a, ph) do { uint32_t _m=(a), _p=(ph), _d;                                   \
    asm volatile("{ .reg .pred p; mbarrier.try_wait.parity.acquire.cta.shared::cta.b64 p, [%1], %2; selp.b32 %0,1,0,p; }" \
                 : "=r"(_d) : "r"(_m), "r"(_p) : "memory");                                   \
    if (!_d) {                                                                                \
      asm volatile("{ .reg .pred P1; WL%=: mbarrier.try_wait.parity.acquire.cta.shared::cta.b64 P1, [%0], %1, 0x989680; @P1 bra.uni WD%=; bra.uni WL%=; WD%=: }" \
                   :: "r"(_m), "r"(_p) : "memory"); } } while(0)
#define BULK_G2S(d, s, n, m) \
    asm volatile("cp.async.bulk.shared::cta.global.mbarrier::complete_tx::bytes [%0], [%1], %2, [%3];" \
                 :: "r"(d), "l"(s), "r"(n), "r"(m) : "memory")
#define LDSM_X4(r0, r1, r2, r3, a) \
    asm volatile("ldmatrix.sync.aligned.m8n8.x4.shared.b16 {%0,%1,%2,%3}, [%4];" \
                 : "=r"(r0), "=r"(r1), "=r"(r2), "=r"(r3) : "r"(a))
#define LDSM_X4T(r0, r1, r2, r3, a) \
    asm volatile("ldmatrix.sync.aligned.m8n8.x4.trans.shared.b16 {%0,%1,%2,%3}, [%4];" \
                 : "=r"(r0), "=r"(r1), "=r"(r2), "=r"(r3) : "r"(a))
#define MMA16816H(d, av, bv) \
    asm volatile("mma.sync.aligned.m16n8k16.row.col.f32.f16.f16.f32 " \
                 "{%0,%1,%2,%3}, {%4,%5,%6,%7}, {%8,%9}, {%0,%1,%2,%3};" \
                 : "+f"((d)[0]), "+f"((d)[1]), "+f"((d)[2]), "+f"((d)[3]) \
                 : "r"((av)[0]), "r"((av)[1]), "r"((av)[2]), "r"((av)[3]), \
                   "r"((bv)[0]), "r"((bv)[1]))

// ---------------- fp16 pack helpers --------------------------------------------
__device__ __forceinline__ uint32_t h2pack(float v0, float v1) {
    return (uint32_t)__half_as_ushort(__float2half_rn(v0))
         | ((uint32_t)__half_as_ushort(__float2half_rn(v1)) << 16);
}
__device__ __forceinline__ void pack4H(char* base, int ktK, int m, int n, float4 v) {
    const int mt = m >> 7, mr = m & 127;
    const int kt = n >> 6, c = n & 63;
    const size_t tb = ((size_t)mt * ktK + kt) * 16384;
    uint32_t off = (uint32_t)(mr * 128 + c * 2);
    off ^= (off >> 3) & 0x70;
    *(uint2*)(base + tb + off) = make_uint2(h2pack(v.x, v.y), h2pack(v.z, v.w));
}
__device__ __forceinline__ void pack2H(char* base, int ktK, int m, int n, float v0, float v1) {
    const int mt = m >> 7, mr = m & 127;
    const int kt = n >> 6, c = n & 63;
    const size_t tb = ((size_t)mt * ktK + kt) * 16384;
    uint32_t off = (uint32_t)(mr * 128 + c * 2);
    off ^= (off >> 3) & 0x70;
    *(uint32_t*)(base + tb + off) = h2pack(v0, v1);
}

// ---------------- RMSNorm -> packed fp16 ---------------------------------------
__global__ __launch_bounds__(256) void rmsnorm_pack(
    const float* __restrict__ x, const float* __restrict__ w, __half* __restrict__ dst)
{
    const int row = blockIdx.x;
    const float4* xr = (const float4*)(x + (size_t)row * DD);
    float4 a = xr[threadIdx.x];
    float4 b = xr[threadIdx.x + 256];
    float ss = a.x*a.x + a.y*a.y + a.z*a.z + a.w*a.w
             + b.x*b.x + b.y*b.y + b.z*b.z + b.w*b.w;
    #pragma unroll
    for (int o = 16; o; o >>= 1) ss += __shfl_xor_sync(0xffffffffu, ss, o);
    __shared__ float sred[8];
    if ((threadIdx.x & 31) == 0) sred[threadIdx.x >> 5] = ss;
    __syncthreads();
    float tot = sred[0]+sred[1]+sred[2]+sred[3]+sred[4]+sred[5]+sred[6]+sred[7];
    float sc = rsqrtf(tot * (1.0f / DD) + 1e-5f);

    const float4* wr = (const float4*)w;
    #pragma unroll
    for (int g = 0; g < 2; g++) {
        const int gi = threadIdx.x + g*256;
        float4 v = (g == 0) ? a : b;
        float4 wv = wr[gi];
        v.x *= sc * wv.x; v.y *= sc * wv.y; v.z *= sc * wv.z; v.w *= sc * wv.w;
        pack4H((char*)dst, DD/64, row, gi*4, v);
    }
}

// ---------------- weight fp32 -> fp16 tile-packed (row map m -> m*step + off) ---
__global__ __launch_bounds__(256) void convW(
    const float* __restrict__ src, __half* __restrict__ dst, int K,
    int mstep, int moff, int total4)
{
    int gid = blockIdx.x * 256 + threadIdx.x;
    if (gid >= total4) return;
    const int kq = K >> 2;
    const int m  = gid / kq;
    const int k  = (gid - m * kq) << 2;
    float4 v = *(const float4*)(src + (size_t)m * K + k);
    pack4H((char*)dst, K >> 6, m * mstep + moff, k, v);
}

// ---------------- fp16 mma.sync GEMM --------------------------------------------
// 128x128 tile, 8 math warps + producer; 3 stages; 2 CTAs/SM.
// mode 0: out v(+bias) ; mode 2: E + v + bias (fp32 C)
// mode 3: dual-FFN: B rows interleaved (w1,w3); P <- (v1+bias) + relu(v3+bias3), packed
// out select: P -> packed tiled fp16 ; Hrow -> row-major fp16 ; else fp32 C.
#define G_STG    3
#define G_TB     16384
#define G_SMEM   (1024 + G_STG*2*G_TB)        // 99328
#define GROUP_M  8

__global__ __launch_bounds__(288, 2) void gemm_mma(
    const __half* __restrict__ A2, const __half* __restrict__ B2,
    const float* __restrict__ bias, const float* __restrict__ bias3,
    const float* __restrict__ E,
    float* __restrict__ C, __half* __restrict__ P, __half* __restrict__ Hrow,
    int N, int ktK, int mode)
{
    extern __shared__ char sm[];
    const uint32_t sb = smem_u32(sm);
    const int tid = threadIdx.x, wid = tid >> 5, lane = tid & 31;

    const uint32_t MFULL  = sb;
    const uint32_t MEMPTY = sb + 256;
    const uint32_t SA     = sb + 1024;
    const uint32_t SBq    = SA + G_STG * G_TB;

    if (tid == 0) {
        #pragma unroll
        for (int s = 0; s < G_STG; s++) { MBAR_INIT(MFULL + s*8, 1); MBAR_INIT(MEMPTY + s*8, 8); }
    }
    __syncthreads();

    const int gridN = gridDim.x;
    const int bid   = blockIdx.y * gridN + blockIdx.x;
    const int tpg   = GROUP_M * gridN;
    const int grp   = bid / tpg, rem = bid - grp * tpg;
    const int mt    = grp * GROUP_M + (rem % GROUP_M);
    const int nt    = rem / GROUP_M;

    float d[2][8][4];
    #pragma unroll
    for (int a = 0; a < 2; a++)
        #pragma unroll
        for (int b = 0; b < 8; b++)
            #pragma unroll
            for (int c = 0; c < 4; c++) d[a][b][c] = 0.f;

    if (wid == 8) {
        if (elect_one()) {
            const char* Ag = (const char*)A2 + (size_t)mt * ktK * G_TB;
            const char* Bg = (const char*)B2 + (size_t)nt * ktK * G_TB;
            int s = 0, ph = 1;
            for (int kt = 0; kt < ktK; kt++) {
                MBAR_WAIT(MEMPTY + s*8, ph);
                MBAR_EXPECT(MFULL + s*8, 2*G_TB);
                BULK_G2S(SA  + s*G_TB, Ag + (size_t)kt*G_TB, G_TB, MFULL + s*8);
                BULK_G2S(SBq + s*G_TB, Bg + (size_t)kt*G_TB, G_TB, MFULL + s*8);
                if (++s == G_STG) { s = 0; ph ^= 1; }
            }
        }
    } else {
        const int wm = (wid & 3) * 32;
        const int wn = (wid >> 2) * 64;
        const uint32_t rsub   = (uint32_t)(((lane >> 3) & 1) * 8 + (lane & 7));
        const uint32_t ksel   = (uint32_t)((lane >> 4) * 16);
        const uint32_t cmask  = (uint32_t)((lane & 7) << 4);
        const uint32_t aRowOff = (uint32_t)(wm + rsub) * 128;
        const uint32_t bRowOff = (uint32_t)(wn + rsub) * 128;

        int s = 0, ph = 0;
        for (int kt = 0; kt < ktK; kt++) {
            MBAR_WAIT(MFULL + s*8, ph);
            const uint32_t sa  = SA  + s*G_TB;
            const uint32_t sbb = SBq + s*G_TB;
            #pragma unroll
            for (int kk4 = 0; kk4 < 4; kk4++) {
                const uint32_t ko = (uint32_t)(kk4*32 + ksel) ^ cmask;
                uint32_t af[2][4];
                #pragma unroll
                for (int mi = 0; mi < 2; mi++)
                    LDSM_X4(af[mi][0], af[mi][1], af[mi][2], af[mi][3],
                            sa + aRowOff + mi*2048 + ko);
                uint32_t bf[8][2];
                #pragma unroll
                for (int ng = 0; ng < 4; ng++) {
                    uint32_t t0, t1, t2, t3;
                    LDSM_X4(t0, t1, t2, t3, sbb + bRowOff + ng*2048 + ko);
                    bf[2*ng][0] = t0; bf[2*ng+1][0] = t1;
                    bf[2*ng][1] = t2; bf[2*ng+1][1] = t3;
                }
                #pragma unroll
                for (int mi = 0; mi < 2; mi++)
                    #pragma unroll
                    for (int ni = 0; ni < 8; ni++)
                        MMA16816H(d[mi][ni], af[mi], bf[ni]);
            }
            if (lane == 0) MBAR_ARRIVE(MEMPTY + s*8);
            if (++s == G_STG) { s = 0; ph ^= 1; }
        }
    }

    __syncthreads();

    float* st = (float*)(sm + 1024);
    if (wid < 8) {
        const int wm = (wid & 3) * 32;
        const int wn = (wid >> 2) * 64;
        const int r0 = lane >> 2;
        const int cc = (lane & 3) * 2;
        #pragma unroll
        for (int mi = 0; mi < 2; mi++)
            #pragma unroll
            for (int ni = 0; ni < 8; ni++) {
                const int r = wm + mi*16 + r0;
                const int c = wn + ni*8 + cc;
                st[r*132 + c]       = d[mi][ni][0];
                st[r*132 + c + 1]   = d[mi][ni][1];
                st[(r+8)*132 + c]   = d[mi][ni][2];
                st[(r+8)*132 + c+1] = d[mi][ni][3];
            }
    }
    __syncthreads();

    if (mode == 3) {
        // dual-FFN combine: even cols = a1, odd cols = a3
        if (tid < 256) {
            const int r0 = tid >> 4;            // 0..15
            const int cg = (tid & 15) * 4;      // logical n group of 4
            const int nG = nt*64 + cg;
            float4 b1v = *(const float4*)(bias  + nG);
            float4 b3v = *(const float4*)(bias3 + nG);
            #pragma unroll 4
            for (int rp = 0; rp < 8; rp++) {
                const int r = rp*16 + r0;
                float4 u0 = *(float4*)&st[r*132 + cg*2];
                float4 u1 = *(float4*)&st[r*132 + cg*2 + 4];
                float4 g;
                g.x = (u0.x + b1v.x) + fmaxf(u0.y + b3v.x, 0.f);
                g.y = (u0.z + b1v.y) + fmaxf(u0.w + b3v.y, 0.f);
                g.z = (u1.x + b1v.z) + fmaxf(u1.y + b3v.z, 0.f);
                g.w = (u1.z + b1v.w) + fmaxf(u1.w + b3v.w, 0.f);
                pack4H((char*)P, FF/64, mt*128 + r, nG, g);
            }
        }
    } else if (tid < 256) {
        const int r0 = tid >> 5;
        const int c  = (tid & 31) * 4;
        const int n  = nt*128 + c;
        float4 bv = make_float4(0.f, 0.f, 0.f, 0.f);
        if (bias) bv = *(const float4*)(bias + n);
        #pragma unroll 4
        for (int rp = 0; rp < 16; rp++) {
            const int r = rp*8 + r0;
            const size_t idx = (size_t)(mt*128 + r) * N + n;
            float4 v = *(float4*)&st[r*132 + c];
            v.x += bv.x; v.y += bv.y; v.z += bv.z; v.w += bv.w;
            if (mode == 2) {
                float4 e = *(const float4*)(E + idx);
                v.x += e.x; v.y += e.y; v.z += e.z; v.w += e.w;
            }
            if (P)         pack4H((char*)P, N >> 6, mt*128 + r, n, v);
            else if (Hrow) *(uint2*)(Hrow + idx) = make_uint2(h2pack(v.x, v.y), h2pack(v.z, v.w));
            else           *(float4*)(C + idx) = v;
        }
    }
}

// ---------------- fp16 tensor-core causal flash attention -> packed -------------
#define AT_SMEM (3*16384 + 8192 + 64*68*4 + 512 + 1024)   // ~76KB
#define ASCALE  0.08838834764831845f

__global__ __launch_bounds__(256, 2) void attn_fp16(
    const __half* __restrict__ qkvh, __half* __restrict__ outP)
{
    extern __shared__ char smc[];
    const uint32_t qb = smem_u32(smc);
    const uint32_t kb = qb + 16384;
    const uint32_t vb = kb + 16384;
    const uint32_t pb = vb + 16384;
    float* Sb = (float*)(smc + 3*16384 + 8192);
    float* Cr = Sb + 64*68;
    float* Ll = Cr + 64;

    const int tid = threadIdx.x, wid = tid >> 5, lane = tid & 31;
    const int qt = (int)gridDim.x - 1 - (int)blockIdx.x;   // longest CTAs first
    const int hh = blockIdx.y, bb = blockIdx.z;
    const int q0 = qt * 64;

    #pragma unroll
    for (int i = 0; i < 4; i++) {
        const int id = i*256 + tid;
        const int rr = id >> 4, oc = id & 15;
        uint4 v = *(const uint4*)(qkvh + (size_t)(bb*SS + q0 + rr) * QKVW + hh*HD + oc*8);
        uint32_t off = (uint32_t)(rr*128 + (oc & 7)*16);
        off ^= (off >> 3) & 0x70;
        *(uint4*)(smc + (size_t)(oc >> 3)*8192 + off) = v;
    }

    const int srow = tid >> 2;
    const int sg   = tid & 3;
    float mrun = -INFINITY, lrun = 0.f;

    float o[8][4];
    #pragma unroll
    for (int i = 0; i < 8; i++)
        #pragma unroll
        for (int j = 0; j < 4; j++) o[i][j] = 0.f;

    const int wm  = (wid & 3) * 16;
    const int wnk = (wid >> 2) * 32;
    const int wnv = (wid >> 2) * 64;
    const int rA0 = wm + lane/4, rA1 = rA0 + 8;
    const uint32_t rsub  = (uint32_t)(((lane >> 3) & 1) * 8 + (lane & 7));
    const uint32_t ksel  = (uint32_t)((lane >> 4) * 16);
    const uint32_t cmask = (uint32_t)((lane & 7) << 4);
    const uint32_t aRowOff = (uint32_t)(wm + rsub) * 128;
    const int vrow = lane & 15;
    const int voct = lane >> 4;

    const int njt = qt + 1;
    for (int jt = 0; jt < njt; jt++) {
        const int j0 = jt * 64;
        __syncthreads();
        #pragma unroll
        for (int i = 0; i < 4; i++) {
            const int id = i*256 + tid;
            const int rr = id >> 4, oc = id & 15;
            const __half* base = qkvh + (size_t)(bb*SS + j0 + rr) * QKVW + hh*HD + oc*8;
            uint4 kvv = *(const uint4*)(base + 16*HD);
            uint4 vvv = *(const uint4*)(base + 32*HD);
            uint32_t off = (uint32_t)(rr*128 + (oc & 7)*16);
            off ^= (off >> 3) & 0x70;
            const size_t toff = (size_t)(oc >> 3)*8192 + off;
            *(uint4*)(smc + 16384 + toff) = kvv;
            *(uint4*)(smc + 32768 + toff) = vvv;
        }
        __syncthreads();

        {
            float c[4][4];
            #pragma unroll
            for (int i = 0; i < 4; i++)
                #pragma unroll
                for (int j = 0; j < 4; j++) c[i][j] = 0.f;
            #pragma unroll
            for (int t = 0; t < 2; t++) {
                #pragma unroll
                for (int kk4 = 0; kk4 < 4; kk4++) {
                    const uint32_t ko = (uint32_t)(kk4*32 + ksel) ^ cmask;
                    uint32_t af[4];
                    LDSM_X4(af[0], af[1], af[2], af[3], qb + t*8192 + aRowOff + ko);
                    uint32_t bf[4][2];
                    #pragma unroll
                    for (int ng = 0; ng < 2; ng++) {
                        uint32_t t0, t1, t2, t3;
                        LDSM_X4(t0, t1, t2, t3,
                                kb + t*8192 + (uint32_t)(wnk + ng*16 + rsub)*128 + ko);
                        bf[2*ng][0] = t0; bf[2*ng+1][0] = t1;
                        bf[2*ng][1] = t2; bf[2*ng+1][1] = t3;
                    }
                    #pragma unroll
                    for (int ntl = 0; ntl < 4; ntl++)
                        MMA16816H(c[ntl], af, bf[ntl]);
                }
            }
            const int cc = (lane & 3) * 2;
            #pragma unroll
            for (int ntl = 0; ntl < 4; ntl++) {
                const int cb = wnk + ntl*8 + cc;
                Sb[rA0*68 + cb]     = c[ntl][0];
                Sb[rA0*68 + cb + 1] = c[ntl][1];
                Sb[rA1*68 + cb]     = c[ntl][2];
                Sb[rA1*68 + cb + 1] = c[ntl][3];
            }
        }
        __syncthreads();

        {
            const bool diag = (jt == qt);
            float pv[16];
            float mx = -INFINITY;
            #pragma unroll
            for (int t = 0; t < 16; t++) {
                const int cidx = sg*16 + t;
                float v = Sb[srow*68 + cidx] * ASCALE;
                if (diag && cidx > srow) v = -INFINITY;
                pv[t] = v;
                mx = fmaxf(mx, v);
            }
            mx = fmaxf(mx, __shfl_xor_sync(0xffffffffu, mx, 1));
            mx = fmaxf(mx, __shfl_xor_sync(0xffffffffu, mx, 2));
            const float mNew = fmaxf(mrun, mx);
            const float corr = __expf(mrun - mNew);
            float ls = 0.f;
            #pragma unroll
            for (int t2 = 0; t2 < 8; t2++) {
                float p0 = (pv[2*t2]   == -INFINITY) ? 0.f : __expf(pv[2*t2]   - mNew);
                float p1 = (pv[2*t2+1] == -INFINITY) ? 0.f : __expf(pv[2*t2+1] - mNew);
                ls += p0 + p1;
                uint32_t off = (uint32_t)(srow*128 + (sg*16 + 2*t2)*2);
                off ^= (off >> 3) & 0x70;
                *(uint32_t*)(smc + 3*16384 + off) = h2pack(p0, p1);
            }
            ls += __shfl_xor_sync(0xffffffffu, ls, 1);
            ls += __shfl_xor_sync(0xffffffffu, ls, 2);
            lrun = lrun * corr + ls;
            mrun = mNew;
            if (sg == 0) { Cr[srow] = corr; Ll[srow] = lrun; }
        }
        __syncthreads();

        {
            const float c0 = Cr[rA0], c1 = Cr[rA1];
            #pragma unroll
            for (int i = 0; i < 8; i++) {
                o[i][0] *= c0; o[i][1] *= c0;
                o[i][2] *= c1; o[i][3] *= c1;
            }
            const uint32_t vtile = vb + (uint32_t)(wnv >> 6) * 8192;
            #pragma unroll
            for (int kk4 = 0; kk4 < 4; kk4++) {
                const uint32_t ko = (uint32_t)(kk4*32 + ksel) ^ cmask;
                uint32_t af[4];
                LDSM_X4(af[0], af[1], af[2], af[3], pb + aRowOff + ko);
                const int row = kk4*16 + vrow;
                const uint32_t rkey = (uint32_t)((row & 7) << 4);
                #pragma unroll
                for (int pair = 0; pair < 4; pair++) {
                    const uint32_t bcol = (uint32_t)(pair*32 + voct*16) ^ rkey;
                    uint32_t t0, t1, t2, t3;
                    LDSM_X4T(t0, t1, t2, t3, vtile + (uint32_t)row*128 + bcol);
                    uint32_t b0[2] = {t0, t1};
                    uint32_t b1[2] = {t2, t3};
                    MMA16816H(o[pair*2],     af, b0);
                    MMA16816H(o[pair*2 + 1], af, b1);
                }
            }
        }
    }
    __syncthreads();

    {
        const float inv0 = 1.f / Ll[rA0];
        const float inv1 = 1.f / Ll[rA1];
        const int t0i = (bb*HH + hh)*SS + q0 + rA0;
        const int t1i = (bb*HH + hh)*SS + q0 + rA1;
        const int m0 = t0i >> 4, cB0 = (t0i & 15) * 128;
        const int m1 = t1i >> 4, cB1 = (t1i & 15) * 128;
        const int cc = (lane & 3) * 2;
        #pragma unroll
        for (int ntl = 0; ntl < 8; ntl++) {
            const int cb = wnv + ntl*8 + cc;
            pack2H((char*)outP, DD/64, m0, cB0 + cb, o[ntl][0]*inv0, o[ntl][1]*inv0);
            pack2H((char*)outP, DD/64, m1, cB1 + cb, o[ntl][2]*inv1, o[ntl][3]*inv1);
        }
    }
}

// ---------------- launch --------------------------------------------------------
extern "C" void kernel_launch(void* const* d_in, const int* in_sizes, int n_in,
                              void* d_out, int out_size)
{
    (void)in_sizes; (void)n_in; (void)out_size;
    const float* x     = (const float*)d_in[0];
    const float* rms_w = (const float*)d_in[1];
    const float* w_qkv = (const float*)d_in[2];
    const float* w_out = (const float*)d_in[3];
    const float* w1    = (const float*)d_in[4];
    const float* b1    = (const float*)d_in[5];
    const float* w3    = (const float*)d_in[6];
    const float* b3    = (const float*)d_in[7];
    const float* w2    = (const float*)d_in[8];
    const float* b2    = (const float*)d_in[9];
    float* out = (float*)d_out;

    __half *qkvh,*xn2,*att2,*h2,*gg2,*wqkv2,*wout2,*w132,*w22;
    cudaGetSymbolAddress((void**)&qkvh,  g_qkvh);
    cudaGetSymbolAddress((void**)&xn2,   g_xn2);
    cudaGetSymbolAddress((void**)&att2,  g_att2);
    cudaGetSymbolAddress((void**)&h2,    g_h2);
    cudaGetSymbolAddress((void**)&gg2,   g_gg2);
    cudaGetSymbolAddress((void**)&wqkv2, g_wqkv2);
    cudaGetSymbolAddress((void**)&wout2, g_wout2);
    cudaGetSymbolAddress((void**)&w132,  g_w132);
    cudaGetSymbolAddress((void**)&w22,   g_w22);

    cudaFuncSetAttribute(gemm_mma, cudaFuncAttributeMaxDynamicSharedMemorySize, G_SMEM);
    cudaFuncSetAttribute(attn_fp16, cudaFuncAttributeMaxDynamicSharedMemorySize, AT_SMEM);

    // weight conversions
    convW<<<(QKVW*DD/4 + 255)/256, 256>>>(w_qkv, wqkv2, DD, 1, 0, QKVW*DD/4);
    convW<<<(DD*DD/4   + 255)/256, 256>>>(w_out, wout2, DD, 1, 0, DD*DD/4);
    convW<<<(FF*DD/4   + 255)/256, 256>>>(w1,    w132,  DD, 2, 0, FF*DD/4);
    convW<<<(FF*DD/4   + 255)/256, 256>>>(w3,    w132,  DD, 2, 1, FF*DD/4);
    convW<<<(DD*FF/4   + 255)/256, 256>>>(w2,    w22,   FF, 1, 0, DD*FF/4);

    // 1) RMSNorm -> packed
    rmsnorm_pack<<<MM, 256>>>(x, rms_w, xn2);

    // 2) QKV projection -> fp16 row-major
    gemm_mma<<<dim3(QKVW/128, MM/128), 288, G_SMEM>>>(
        xn2, wqkv2, nullptr, nullptr, nullptr, nullptr, nullptr, qkvh, QKVW, DD/64, 0);

    // 3) attention (fp16 tensor cores) -> packed att2
    attn_fp16<<<dim3(SS/64, HH, BB), 256, AT_SMEM>>>(qkvh, att2);

    // 4) out projection -> packed h2
    gemm_mma<<<dim3(DD/128, MM/128), 288, G_SMEM>>>(
        att2, wout2, nullptr, nullptr, nullptr, nullptr, h2, nullptr, DD, DD/64, 0);

    // 5+6) fused dual-FFN: gg = (h@w1^T + b1) + relu(h@w3^T + b3) -> packed gg2
    gemm_mma<<<dim3(2*FF/128, MM/128), 288, G_SMEM>>>(
        h2, w132, b1, b3, nullptr, nullptr, gg2, nullptr, 2*FF, DD/64, 3);

    // 7) out = x + gg @ w2^T + b2 (fp32 final)
    gemm_mma<<<dim3(DD/128, MM/128), 288, G_SMEM>>>(
        gg2, w22, b2, nullptr, x, out, nullptr, nullptr, DD, FF/64, 2);
}

// round 12
// speedup vs baseline: 2.2338x; 1.0060x over previous
#include <cuda_runtime.h>
#include <cuda_fp16.h>
#include <math.h>
#include <stdint.h>

#define BB   2
#define SS   2048
#define DD   2048
#define HH   16
#define HD   128
#define FF   8192
#define MM   (BB*SS)          // 4096
#define QKVW (3*DD)           // 6144

// ---------------- scratch ----------------
__device__ __half g_qkvh[(size_t)MM*QKVW];     // fp16 row-major qkv
// fp16 packed (tiled [rows/128][K/64][128][64], SW128)
__device__ __half g_xn2 [(size_t)MM*DD];
__device__ __half g_att2[(size_t)MM*DD];
__device__ __half g_h2  [(size_t)MM*DD];
__device__ __half g_gg2 [(size_t)MM*FF];
__device__ __half g_wqkv2[(size_t)QKVW*DD];
__device__ __half g_wout2[(size_t)DD*DD];
__device__ __half g_w132[(size_t)2*FF*DD];     // w1/w3 row-interleaved
__device__ __half g_w22 [(size_t)DD*FF];

// ---------------- PTX helpers -------------------------------------------------
__device__ __forceinline__ uint32_t smem_u32(const void* p) {
    uint32_t a;
    asm("{ .reg .u64 t; cvta.to.shared.u64 t, %1; cvt.u32.u64 %0, t; }" : "=r"(a) : "l"(p));
    return a;
}
__device__ __forceinline__ uint32_t elect_one() {
    uint32_t p;
    asm volatile("{ .reg .pred p; elect.sync _|p, 0xFFFFFFFF; selp.b32 %0,1,0,p; }" : "=r"(p));
    return p;
}
#define MBAR_INIT(a, c) \
    asm volatile("mbarrier.init.shared.b64 [%0], %1;" :: "r"(a), "r"(c) : "memory")
#define MBAR_EXPECT(a, b) \
    asm volatile("mbarrier.arrive.expect_tx.shared.b64 _, [%0], %1;" :: "r"(a), "r"(b) : "memory")
#define MBAR_ARRIVE(a) \
    asm volatile("mbarrier.arrive.shared.b64 _, [%0];" :: "r"(a) : "memory")
#define MBAR_WAIT(a, ph) do { uint32_t _m=(a), _p=(ph), _d;                                   \
    asm volatile("{ .reg .pred p; mbarrier.try_wait.parity.acquire.cta.shared::cta.b64 p, [%1], %2; selp.b32 %0,1,0,p; }" \
                 : "=r"(_d) : "r"(_m), "r"(_p) : "memory");                                   \
    if (!_d) {                                                                                \
      asm volatile("{ .reg .pred P1; WL%=: mbarrier.try_wait.parity.acquire.cta.shared::cta.b64 P1, [%0], %1, 0x989680; @P1 bra.uni WD%=; bra.uni WL%=; WD%=: }" \
                   :: "r"(_m), "r"(_p) : "memory"); } } while(0)
#define BULK_G2S(d, s, n, m) \
    asm volatile("cp.async.bulk.shared::cta.global.mbarrier::complete_tx::bytes [%0], [%1], %2, [%3];" \
                 :: "r"(d), "l"(s), "r"(n), "r"(m) : "memory")
#define LDSM_X4(r0, r1, r2, r3, a) \
    asm volatile("ldmatrix.sync.aligned.m8n8.x4.shared.b16 {%0,%1,%2,%3}, [%4];" \
                 : "=r"(r0), "=r"(r1), "=r"(r2), "=r"(r3) : "r"(a))
#define LDSM_X4T(r0, r1, r2, r3, a) \
    asm volatile("ldmatrix.sync.aligned.m8n8.x4.trans.shared.b16 {%0,%1,%2,%3}, [%4];" \
                 : "=r"(r0), "=r"(r1), "=r"(r2), "=r"(r3) : "r"(a))
#define MMA16816H(d, av, bv) \
    asm volatile("mma.sync.aligned.m16n8k16.row.col.f32.f16.f16.f32 " \
                 "{%0,%1,%2,%3}, {%4,%5,%6,%7}, {%8,%9}, {%0,%1,%2,%3};" \
                 : "+f"((d)[0]), "+f"((d)[1]), "+f"((d)[2]), "+f"((d)[3]) \
                 : "r"((av)[0]), "r"((av)[1]), "r"((av)[2]), "r"((av)[3]), \
                   "r"((bv)[0]), "r"((bv)[1]))

// ---------------- fp16 pack helpers --------------------------------------------
__device__ __forceinline__ uint32_t h2pack(float v0, float v1) {
    return (uint32_t)__half_as_ushort(__float2half_rn(v0))
         | ((uint32_t)__half_as_ushort(__float2half_rn(v1)) << 16);
}
__device__ __forceinline__ void pack4H(char* base, int ktK, int m, int n, float4 v) {
    const int mt = m >> 7, mr = m & 127;
    const int kt = n >> 6, c = n & 63;
    const size_t tb = ((size_t)mt * ktK + kt) * 16384;
    uint32_t off = (uint32_t)(mr * 128 + c * 2);
    off ^= (off >> 3) & 0x70;
    *(uint2*)(base + tb + off) = make_uint2(h2pack(v.x, v.y), h2pack(v.z, v.w));
}
__device__ __forceinline__ void pack2H(char* base, int ktK, int m, int n, float v0, float v1) {
    const int mt = m >> 7, mr = m & 127;
    const int kt = n >> 6, c = n & 63;
    const size_t tb = ((size_t)mt * ktK + kt) * 16384;
    uint32_t off = (uint32_t)(mr * 128 + c * 2);
    off ^= (off >> 3) & 0x70;
    *(uint32_t*)(base + tb + off) = h2pack(v0, v1);
}

// ---------------- RMSNorm -> packed fp16 ---------------------------------------
__global__ __launch_bounds__(256) void rmsnorm_pack(
    const float* __restrict__ x, const float* __restrict__ w, __half* __restrict__ dst)
{
    const int row = blockIdx.x;
    const float4* xr = (const float4*)(x + (size_t)row * DD);
    float4 a = xr[threadIdx.x];
    float4 b = xr[threadIdx.x + 256];
    float ss = a.x*a.x + a.y*a.y + a.z*a.z + a.w*a.w
             + b.x*b.x + b.y*b.y + b.z*b.z + b.w*b.w;
    #pragma unroll
    for (int o = 16; o; o >>= 1) ss += __shfl_xor_sync(0xffffffffu, ss, o);
    __shared__ float sred[8];
    if ((threadIdx.x & 31) == 0) sred[threadIdx.x >> 5] = ss;
    __syncthreads();
    float tot = sred[0]+sred[1]+sred[2]+sred[3]+sred[4]+sred[5]+sred[6]+sred[7];
    float sc = rsqrtf(tot * (1.0f / DD) + 1e-5f);

    const float4* wr = (const float4*)w;
    #pragma unroll
    for (int g = 0; g < 2; g++) {
        const int gi = threadIdx.x + g*256;
        float4 v = (g == 0) ? a : b;
        float4 wv = wr[gi];
        v.x *= sc * wv.x; v.y *= sc * wv.y; v.z *= sc * wv.z; v.w *= sc * wv.w;
        pack4H((char*)dst, DD/64, row, gi*4, v);
    }
}

// ---------------- all weight conversions in ONE launch --------------------------
// segment sizes (float4 units): qkv 3145728 | wout 1048576 | w1 4194304 | w3 4194304 | w2 4194304
__global__ __launch_bounds__(256) void convAll(
    const float* __restrict__ wqkv, const float* __restrict__ wout,
    const float* __restrict__ w1,   const float* __restrict__ w3,
    const float* __restrict__ w2,
    __half* __restrict__ dqkv, __half* __restrict__ dout,
    __half* __restrict__ d13,  __half* __restrict__ d2)
{
    int gid = blockIdx.x * 256 + threadIdx.x;
    const float* src; __half* dst; int K, mstep, moff;
    if (gid < 3145728)       { src = wqkv; dst = dqkv; K = DD; mstep = 1; moff = 0; }
    else if (gid < 4194304)  { src = wout; dst = dout; K = DD; mstep = 1; moff = 0; gid -= 3145728; }
    else if (gid < 8388608)  { src = w1;   dst = d13;  K = DD; mstep = 2; moff = 0; gid -= 4194304; }
    else if (gid < 12582912) { src = w3;   dst = d13;  K = DD; mstep = 2; moff = 1; gid -= 8388608; }
    else                     { src = w2;   dst = d2;   K = FF; mstep = 1; moff = 0; gid -= 12582912; }
    const int kq = K >> 2;
    const int m  = gid / kq;
    const int k  = (gid - m * kq) << 2;
    float4 v = *(const float4*)(src + (size_t)m * K + k);
    pack4H((char*)dst, K >> 6, m * mstep + moff, k, v);
}

// ---------------- fp16 mma.sync GEMM --------------------------------------------
#define G_STG    3
#define G_TB     16384
#define G_SMEM   (1024 + G_STG*2*G_TB)        // 99328
#define GROUP_M  8

__global__ __launch_bounds__(288, 2) void gemm_mma(
    const __half* __restrict__ A2, const __half* __restrict__ B2,
    const float* __restrict__ bias, const float* __restrict__ bias3,
    const float* __restrict__ E,
    float* __restrict__ C, __half* __restrict__ P, __half* __restrict__ Hrow,
    int N, int ktK, int mode)
{
    extern __shared__ char sm[];
    const uint32_t sb = smem_u32(sm);
    const int tid = threadIdx.x, wid = tid >> 5, lane = tid & 31;

    const uint32_t MFULL  = sb;
    const uint32_t MEMPTY = sb + 256;
    const uint32_t SA     = sb + 1024;
    const uint32_t SBq    = SA + G_STG * G_TB;

    if (tid == 0) {
        #pragma unroll
        for (int s = 0; s < G_STG; s++) { MBAR_INIT(MFULL + s*8, 1); MBAR_INIT(MEMPTY + s*8, 8); }
    }
    __syncthreads();

    const int gridN = gridDim.x;
    const int bid   = blockIdx.y * gridN + blockIdx.x;
    const int tpg   = GROUP_M * gridN;
    const int grp   = bid / tpg, rem = bid - grp * tpg;
    const int mt    = grp * GROUP_M + (rem % GROUP_M);
    const int nt    = rem / GROUP_M;

    float d[2][8][4];
    #pragma unroll
    for (int a = 0; a < 2; a++)
        #pragma unroll
        for (int b = 0; b < 8; b++)
            #pragma unroll
            for (int c = 0; c < 4; c++) d[a][b][c] = 0.f;

    if (wid == 8) {
        if (elect_one()) {
            const char* Ag = (const char*)A2 + (size_t)mt * ktK * G_TB;
            const char* Bg = (const char*)B2 + (size_t)nt * ktK * G_TB;
            int s = 0, ph = 1;
            for (int kt = 0; kt < ktK; kt++) {
                MBAR_WAIT(MEMPTY + s*8, ph);
                MBAR_EXPECT(MFULL + s*8, 2*G_TB);
                BULK_G2S(SA  + s*G_TB, Ag + (size_t)kt*G_TB, G_TB, MFULL + s*8);
                BULK_G2S(SBq + s*G_TB, Bg + (size_t)kt*G_TB, G_TB, MFULL + s*8);
                if (++s == G_STG) { s = 0; ph ^= 1; }
            }
        }
    } else {
        const int wm = (wid & 3) * 32;
        const int wn = (wid >> 2) * 64;
        const uint32_t rsub   = (uint32_t)(((lane >> 3) & 1) * 8 + (lane & 7));
        const uint32_t ksel   = (uint32_t)((lane >> 4) * 16);
        const uint32_t cmask  = (uint32_t)((lane & 7) << 4);
        const uint32_t aRowOff = (uint32_t)(wm + rsub) * 128;
        const uint32_t bRowOff = (uint32_t)(wn + rsub) * 128;

        int s = 0, ph = 0;
        for (int kt = 0; kt < ktK; kt++) {
            MBAR_WAIT(MFULL + s*8, ph);
            const uint32_t sa  = SA  + s*G_TB;
            const uint32_t sbb = SBq + s*G_TB;
            #pragma unroll
            for (int kk4 = 0; kk4 < 4; kk4++) {
                const uint32_t ko = (uint32_t)(kk4*32 + ksel) ^ cmask;
                uint32_t af[2][4];
                #pragma unroll
                for (int mi = 0; mi < 2; mi++)
                    LDSM_X4(af[mi][0], af[mi][1], af[mi][2], af[mi][3],
                            sa + aRowOff + mi*2048 + ko);
                uint32_t bf[8][2];
                #pragma unroll
                for (int ng = 0; ng < 4; ng++) {
                    uint32_t t0, t1, t2, t3;
                    LDSM_X4(t0, t1, t2, t3, sbb + bRowOff + ng*2048 + ko);
                    bf[2*ng][0] = t0; bf[2*ng+1][0] = t1;
                    bf[2*ng][1] = t2; bf[2*ng+1][1] = t3;
                }
                #pragma unroll
                for (int mi = 0; mi < 2; mi++)
                    #pragma unroll
                    for (int ni = 0; ni < 8; ni++)
                        MMA16816H(d[mi][ni], af[mi], bf[ni]);
            }
            if (lane == 0) MBAR_ARRIVE(MEMPTY + s*8);
            if (++s == G_STG) { s = 0; ph ^= 1; }
        }
    }

    __syncthreads();

    float* st = (float*)(sm + 1024);
    if (wid < 8) {
        const int wm = (wid & 3) * 32;
        const int wn = (wid >> 2) * 64;
        const int r0 = lane >> 2;
        const int cc = (lane & 3) * 2;
        #pragma unroll
        for (int mi = 0; mi < 2; mi++)
            #pragma unroll
            for (int ni = 0; ni < 8; ni++) {
                const int r = wm + mi*16 + r0;
                const int c = wn + ni*8 + cc;
                st[r*132 + c]       = d[mi][ni][0];
                st[r*132 + c + 1]   = d[mi][ni][1];
                st[(r+8)*132 + c]   = d[mi][ni][2];
                st[(r+8)*132 + c+1] = d[mi][ni][3];
            }
    }
    __syncthreads();

    if (mode == 3) {
        if (tid < 256) {
            const int r0 = tid >> 4;
            const int cg = (tid & 15) * 4;
            const int nG = nt*64 + cg;
            float4 b1v = *(const float4*)(bias  + nG);
            float4 b3v = *(const float4*)(bias3 + nG);
            #pragma unroll 4
            for (int rp = 0; rp < 8; rp++) {
                const int r = rp*16 + r0;
                float4 u0 = *(float4*)&st[r*132 + cg*2];
                float4 u1 = *(float4*)&st[r*132 + cg*2 + 4];
                float4 g;
                g.x = (u0.x + b1v.x) + fmaxf(u0.y + b3v.x, 0.f);
                g.y = (u0.z + b1v.y) + fmaxf(u0.w + b3v.y, 0.f);
                g.z = (u1.x + b1v.z) + fmaxf(u1.y + b3v.z, 0.f);
                g.w = (u1.z + b1v.w) + fmaxf(u1.w + b3v.w, 0.f);
                pack4H((char*)P, FF/64, mt*128 + r, nG, g);
            }
        }
    } else if (tid < 256) {
        const int r0 = tid >> 5;
        const int c  = (tid & 31) * 4;
        const int n  = nt*128 + c;
        float4 bv = make_float4(0.f, 0.f, 0.f, 0.f);
        if (bias) bv = *(const float4*)(bias + n);
        #pragma unroll 4
        for (int rp = 0; rp < 16; rp++) {
            const int r = rp*8 + r0;
            const size_t idx = (size_t)(mt*128 + r) * N + n;
            float4 v = *(float4*)&st[r*132 + c];
            v.x += bv.x; v.y += bv.y; v.z += bv.z; v.w += bv.w;
            if (mode == 2) {
                float4 e = *(const float4*)(E + idx);
                v.x += e.x; v.y += e.y; v.z += e.z; v.w += e.w;
            }
            if (P)         pack4H((char*)P, N >> 6, mt*128 + r, n, v);
            else if (Hrow) *(uint2*)(Hrow + idx) = make_uint2(h2pack(v.x, v.y), h2pack(v.z, v.w));
            else           *(float4*)(C + idx) = v;
        }
    }
}

// ---------------- fp16 causal flash attention, double-buffered K/V --------------
// smem: Q 16K | K0 16K | K1 16K | V0 16K | V1 16K | P 8K | Sb 17408 | Cr/Ll 512
#define AT_SMEM (5*16384 + 8192 + 64*68*4 + 512)     // 108032
#define ASCALE  0.08838834764831845f

__global__ __launch_bounds__(256, 2) void attn_fp16(
    const __half* __restrict__ qkvh, __half* __restrict__ outP)
{
    extern __shared__ char smc[];
    const uint32_t qb = smem_u32(smc);
    const uint32_t pb = qb + 81920;
    float* Sb = (float*)(smc + 90112);
    float* Cr = Sb + 64*68;
    float* Ll = Cr + 64;

    const int tid = threadIdx.x, wid = tid >> 5, lane = tid & 31;
    const int qt = (int)gridDim.x - 1 - (int)blockIdx.x;   // longest CTAs first
    const int hh = blockIdx.y, bb = blockIdx.z;
    const int q0 = qt * 64;

    // ---- preload Q and K/V(jt=0)
    #pragma unroll
    for (int i = 0; i < 4; i++) {
        const int id = i*256 + tid;
        const int rr = id >> 4, oc = id & 15;
        uint32_t off = (uint32_t)(rr*128 + (oc & 7)*16);
        off ^= (off >> 3) & 0x70;
        const uint32_t toff = (uint32_t)(oc >> 3)*8192 + off;
        const __half* qbase = qkvh + (size_t)(bb*SS + q0 + rr) * QKVW + hh*HD + oc*8;
        *(uint4*)(smc + toff) = *(const uint4*)qbase;
        const __half* base = qkvh + (size_t)(bb*SS + rr) * QKVW + hh*HD + oc*8;
        *(uint4*)(smc + 16384 + toff) = *(const uint4*)(base + 16*HD);   // K0
        *(uint4*)(smc + 49152 + toff) = *(const uint4*)(base + 32*HD);   // V0
    }
    __syncthreads();

    const int srow = tid >> 2;
    const int sg   = tid & 3;
    float mrun = -INFINITY, lrun = 0.f;

    float o[8][4];
    #pragma unroll
    for (int i = 0; i < 8; i++)
        #pragma unroll
        for (int j = 0; j < 4; j++) o[i][j] = 0.f;

    const int wm  = (wid & 3) * 16;
    const int wnk = (wid >> 2) * 32;
    const int wnv = (wid >> 2) * 64;
    const int rA0 = wm + lane/4, rA1 = rA0 + 8;
    const uint32_t rsub  = (uint32_t)(((lane >> 3) & 1) * 8 + (lane & 7));
    const uint32_t ksel  = (uint32_t)((lane >> 4) * 16);
    const uint32_t cmask = (uint32_t)((lane & 7) << 4);
    const uint32_t aRowOff = (uint32_t)(wm + rsub) * 128;
    const int vrow = lane & 15;
    const int voct = lane >> 4;

    const int njt = qt + 1;
    for (int jt = 0; jt < njt; jt++) {
        const int cur = jt & 1;
        const uint32_t kbc = qb + 16384 + (uint32_t)cur*16384;
        const uint32_t vbc = qb + 49152 + (uint32_t)cur*16384;

        // ---- prefetch next K/V into registers (latency hidden behind QK)
        uint4 kreg[4], vreg[4];
        const bool hn = (jt + 1 < njt);
        if (hn) {
            const int j0n = (jt + 1) * 64;
            #pragma unroll
            for (int i = 0; i < 4; i++) {
                const int id = i*256 + tid;
                const int rr = id >> 4, oc = id & 15;
                const __half* base = qkvh + (size_t)(bb*SS + j0n + rr) * QKVW + hh*HD + oc*8;
                kreg[i] = *(const uint4*)(base + 16*HD);
                vreg[i] = *(const uint4*)(base + 32*HD);
            }
        }

        // ---- QK^T (fp16 mma): scores 64x64
        {
            float c[4][4];
            #pragma unroll
            for (int i = 0; i < 4; i++)
                #pragma unroll
                for (int j = 0; j < 4; j++) c[i][j] = 0.f;
            #pragma unroll
            for (int t = 0; t < 2; t++) {
                #pragma unroll
                for (int kk4 = 0; kk4 < 4; kk4++) {
                    const uint32_t ko = (uint32_t)(kk4*32 + ksel) ^ cmask;
                    uint32_t af[4];
                    LDSM_X4(af[0], af[1], af[2], af[3], qb + t*8192 + aRowOff + ko);
                    uint32_t bf[4][2];
                    #pragma unroll
                    for (int ng = 0; ng < 2; ng++) {
                        uint32_t t0, t1, t2, t3;
                        LDSM_X4(t0, t1, t2, t3,
                                kbc + t*8192 + (uint32_t)(wnk + ng*16 + rsub)*128 + ko);
                        bf[2*ng][0] = t0; bf[2*ng+1][0] = t1;
                        bf[2*ng][1] = t2; bf[2*ng+1][1] = t3;
                    }
                    #pragma unroll
                    for (int ntl = 0; ntl < 4; ntl++)
                        MMA16816H(c[ntl], af, bf[ntl]);
                }
            }
            const int cc = (lane & 3) * 2;
            #pragma unroll
            for (int ntl = 0; ntl < 4; ntl++) {
                const int cb = wnk + ntl*8 + cc;
                Sb[rA0*68 + cb]     = c[ntl][0];
                Sb[rA0*68 + cb + 1] = c[ntl][1];
                Sb[rA1*68 + cb]     = c[ntl][2];
                Sb[rA1*68 + cb + 1] = c[ntl][3];
            }
        }
        __syncthreads();   // scores ready; also orders prefetch stores vs prior PV

        // ---- store prefetched K/V into alternate buffers
        if (hn) {
            const uint32_t koff = 16384 + (uint32_t)(cur ^ 1)*16384;
            const uint32_t voff = 49152 + (uint32_t)(cur ^ 1)*16384;
            #pragma unroll
            for (int i = 0; i < 4; i++) {
                const int id = i*256 + tid;
                const int rr = id >> 4, oc = id & 15;
                uint32_t off = (uint32_t)(rr*128 + (oc & 7)*16);
                off ^= (off >> 3) & 0x70;
                const uint32_t toff = (uint32_t)(oc >> 3)*8192 + off;
                *(uint4*)(smc + koff + toff) = kreg[i];
                *(uint4*)(smc + voff + toff) = vreg[i];
            }
        }

        // ---- softmax + write P (fp16, swizzled)
        {
            const bool diag = (jt == qt);
            float pv[16];
            float mx = -INFINITY;
            #pragma unroll
            for (int t = 0; t < 16; t++) {
                const int cidx = sg*16 + t;
                float v = Sb[srow*68 + cidx] * ASCALE;
                if (diag && cidx > srow) v = -INFINITY;
                pv[t] = v;
                mx = fmaxf(mx, v);
            }
            mx = fmaxf(mx, __shfl_xor_sync(0xffffffffu, mx, 1));
            mx = fmaxf(mx, __shfl_xor_sync(0xffffffffu, mx, 2));
            const float mNew = fmaxf(mrun, mx);
            const float corr = __expf(mrun - mNew);
            float ls = 0.f;
            #pragma unroll
            for (int t2 = 0; t2 < 8; t2++) {
                float p0 = (pv[2*t2]   == -INFINITY) ? 0.f : __expf(pv[2*t2]   - mNew);
                float p1 = (pv[2*t2+1] == -INFINITY) ? 0.f : __expf(pv[2*t2+1] - mNew);
                ls += p0 + p1;
                uint32_t off = (uint32_t)(srow*128 + (sg*16 + 2*t2)*2);
                off ^= (off >> 3) & 0x70;
                *(uint32_t*)(smc + 81920 + off) = h2pack(p0, p1);
            }
            ls += __shfl_xor_sync(0xffffffffu, ls, 1);
            ls += __shfl_xor_sync(0xffffffffu, ls, 2);
            lrun = lrun * corr + ls;
            mrun = mNew;
            if (sg == 0) { Cr[srow] = corr; Ll[srow] = lrun; }
        }
        __syncthreads();   // P + prefetch stores visible before PV / next QK

        // ---- PV (fp16 mma, V via ldmatrix.trans)
        {
            const float c0 = Cr[rA0], c1 = Cr[rA1];
            #pragma unroll
            for (int i = 0; i < 8; i++) {
                o[i][0] *= c0; o[i][1] *= c0;
                o[i][2] *= c1; o[i][3] *= c1;
            }
            const uint32_t vtile = vbc + (uint32_t)(wnv >> 6) * 8192;
            #pragma unroll
            for (int kk4 = 0; kk4 < 4; kk4++) {
                const uint32_t ko = (uint32_t)(kk4*32 + ksel) ^ cmask;
                uint32_t af[4];
                LDSM_X4(af[0], af[1], af[2], af[3], pb + aRowOff + ko);
                const int row = kk4*16 + vrow;
                const uint32_t rkey = (uint32_t)((row & 7) << 4);
                #pragma unroll
                for (int pair = 0; pair < 4; pair++) {
                    const uint32_t bcol = (uint32_t)(pair*32 + voct*16) ^ rkey;
                    uint32_t t0, t1, t2, t3;
                    LDSM_X4T(t0, t1, t2, t3, vtile + (uint32_t)row*128 + bcol);
                    uint32_t b0[2] = {t0, t1};
                    uint32_t b1[2] = {t2, t3};
                    MMA16816H(o[pair*2],     af, b0);
                    MMA16816H(o[pair*2 + 1], af, b1);
                }
            }
        }
    }
    __syncthreads();

    // ---- normalize + packed store (raw-reshape [B*S, D] mapping)
    {
        const float inv0 = 1.f / Ll[rA0];
        const float inv1 = 1.f / Ll[rA1];
        const int t0i = (bb*HH + hh)*SS + q0 + rA0;
        const int t1i = (bb*HH + hh)*SS + q0 + rA1;
        const int m0 = t0i >> 4, cB0 = (t0i & 15) * 128;
        const int m1 = t1i >> 4, cB1 = (t1i & 15) * 128;
        const int cc = (lane & 3) * 2;
        #pragma unroll
        for (int ntl = 0; ntl < 8; ntl++) {
            const int cb = wnv + ntl*8 + cc;
            pack2H((char*)outP, DD/64, m0, cB0 + cb, o[ntl][0]*inv0, o[ntl][1]*inv0);
            pack2H((char*)outP, DD/64, m1, cB1 + cb, o[ntl][2]*inv1, o[ntl][3]*inv1);
        }
    }
}

// ---------------- launch --------------------------------------------------------
extern "C" void kernel_launch(void* const* d_in, const int* in_sizes, int n_in,
                              void* d_out, int out_size)
{
    (void)in_sizes; (void)n_in; (void)out_size;
    const float* x     = (const float*)d_in[0];
    const float* rms_w = (const float*)d_in[1];
    const float* w_qkv = (const float*)d_in[2];
    const float* w_out = (const float*)d_in[3];
    const float* w1    = (const float*)d_in[4];
    const float* b1    = (const float*)d_in[5];
    const float* w3    = (const float*)d_in[6];
    const float* b3    = (const float*)d_in[7];
    const float* w2    = (const float*)d_in[8];
    const float* b2    = (const float*)d_in[9];
    float* out = (float*)d_out;

    __half *qkvh,*xn2,*att2,*h2,*gg2,*wqkv2,*wout2,*w132,*w22;
    cudaGetSymbolAddress((void**)&qkvh,  g_qkvh);
    cudaGetSymbolAddress((void**)&xn2,   g_xn2);
    cudaGetSymbolAddress((void**)&att2,  g_att2);
    cudaGetSymbolAddress((void**)&h2,    g_h2);
    cudaGetSymbolAddress((void**)&gg2,   g_gg2);
    cudaGetSymbolAddress((void**)&wqkv2, g_wqkv2);
    cudaGetSymbolAddress((void**)&wout2, g_wout2);
    cudaGetSymbolAddress((void**)&w132,  g_w132);
    cudaGetSymbolAddress((void**)&w22,   g_w22);

    cudaFuncSetAttribute(gemm_mma, cudaFuncAttributeMaxDynamicSharedMemorySize, G_SMEM);
    cudaFuncSetAttribute(attn_fp16, cudaFuncAttributeMaxDynamicSharedMemorySize, AT_SMEM);

    // all weight conversions in one launch (16.78M float4 items)
    convAll<<<65536, 256>>>(w_qkv, w_out, w1, w3, w2, wqkv2, wout2, w132, w22);

    // 1) RMSNorm -> packed
    rmsnorm_pack<<<MM, 256>>>(x, rms_w, xn2);

    // 2) QKV projection -> fp16 row-major
    gemm_mma<<<dim3(QKVW/128, MM/128), 288, G_SMEM>>>(
        xn2, wqkv2, nullptr, nullptr, nullptr, nullptr, nullptr, qkvh, QKVW, DD/64, 0);

    // 3) attention (fp16 tensor cores, double-buffered) -> packed att2
    attn_fp16<<<dim3(SS/64, HH, BB), 256, AT_SMEM>>>(qkvh, att2);

    // 4) out projection -> packed h2
    gemm_mma<<<dim3(DD/128, MM/128), 288, G_SMEM>>>(
        att2, wout2, nullptr, nullptr, nullptr, nullptr, h2, nullptr, DD, DD/64, 0);

    // 5+6) fused dual-FFN: gg = (h@w1^T + b1) + relu(h@w3^T + b3) -> packed gg2
    gemm_mma<<<dim3(2*FF/128, MM/128), 288, G_SMEM>>>(
        h2, w132, b1, b3, nullptr, nullptr, gg2, nullptr, 2*FF, DD/64, 3);

    // 7) out = x + gg @ w2^T + b2 (fp32 final)
    gemm_mma<<<dim3(DD/128, MM/128), 288, G_SMEM>>>(
        gg2, w22, b2, nullptr, x, out, nullptr, nullptr, DD, FF/64, 2);
}